// round 3
// baseline (speedup 1.0000x reference)
#include <cuda_runtime.h>
#include <math.h>
#include <stdint.h>

// Problem constants
#define BB 2
#define SS 2048
#define DD 1024
#define HH 16
#define RR 64
#define NN 32
#define RKK 128
#define DHH 64
#define BSZ (BB*SS)          // 4096 tokens
#define NR (NN*RR)           // 2048
#define NRK (NN*RKK)         // 4096
#define LN_EPS 1e-5f

// ---------------- scratch (static __device__; no allocations allowed) -------
__device__ float g_Bqk[DD*NR];       // packed f_qk  [D, N*R]
__device__ float g_Bv [DD*NR];       // packed f_v
__device__ float g_Bkn[DD*NRK];      // packed f_know [D, N*RK]
__device__ float g_WOT[DD*DD];       // W_O^T
__device__ float g_nx [BSZ*DD];      // LN output (reused for LN2)
__device__ float g_allh_qk[BSZ*NR];
__device__ float g_allh_v [BSZ*NR];
__device__ float g_allh_kn[(size_t)BSZ*NRK];
__device__ float g_hq[BSZ*RR], g_hk[BSZ*RR], g_hv[BSZ*RR], g_hkn[BSZ*RKK];
__device__ float g_Tq[BSZ*NR], g_Tk[BSZ*NR], g_Tv[BSZ*NR];
__device__ float g_Tkn[(size_t)BSZ*NRK];
__device__ float g_Q[BSZ*DD], g_K[BSZ*DD], g_V[BSZ*DD];
__device__ float g_attn[BSZ*DD];
__device__ float g_x1[BSZ*DD];

// ---------------- pack f[n,d,r] -> out[d, n*Rr + r] -------------------------
__global__ void pack_f_kernel(const float* __restrict__ in, float* __restrict__ out, int Rr) {
    int total = DD * NN * Rr;
    int idx = blockIdx.x * blockDim.x + threadIdx.x;
    if (idx >= total) return;
    int nr = NN * Rr;
    int d = idx / nr;
    int rem = idx - d * nr;
    int n = rem / Rr;
    int r = rem - n * Rr;
    out[idx] = in[((size_t)n * DD + d) * Rr + r];
}

// ---------------- transpose W_O -> W_O^T ------------------------------------
__global__ void transpose_kernel(const float* __restrict__ in, float* __restrict__ out) {
    __shared__ float tile[32][33];
    int x = blockIdx.x * 32 + threadIdx.x;
    int y = blockIdx.y * 32 + threadIdx.y;
    #pragma unroll
    for (int i = 0; i < 32; i += 8)
        tile[threadIdx.y + i][threadIdx.x] = in[(size_t)(y + i) * DD + x];
    __syncthreads();
    x = blockIdx.y * 32 + threadIdx.x;
    y = blockIdx.x * 32 + threadIdx.y;
    #pragma unroll
    for (int i = 0; i < 32; i += 8)
        out[(size_t)(y + i) * DD + x] = tile[threadIdx.x][threadIdx.y + i];
}

// ---------------- LayerNorm: one block (256 thr) per row of 1024 ------------
__global__ void ln_kernel(const float* __restrict__ x, const float* __restrict__ g,
                          const float* __restrict__ b, float* __restrict__ out) {
    int row = blockIdx.x;
    const float* xr = x + (size_t)row * DD;
    int c = threadIdx.x * 4;
    float4 xv = *(const float4*)(xr + c);
    float s  = xv.x + xv.y + xv.z + xv.w;
    float sq = xv.x*xv.x + xv.y*xv.y + xv.z*xv.z + xv.w*xv.w;
    #pragma unroll
    for (int o = 16; o > 0; o >>= 1) {
        s  += __shfl_xor_sync(0xffffffffu, s,  o);
        sq += __shfl_xor_sync(0xffffffffu, sq, o);
    }
    __shared__ float ss[8], ssq[8];
    __shared__ float mean_s, rstd_s;
    int wid = threadIdx.x >> 5, lid = threadIdx.x & 31;
    if (lid == 0) { ss[wid] = s; ssq[wid] = sq; }
    __syncthreads();
    if (threadIdx.x == 0) {
        float S = 0.f, SQ = 0.f;
        #pragma unroll
        for (int i = 0; i < 8; i++) { S += ss[i]; SQ += ssq[i]; }
        float mu  = S * (1.f / DD);
        float var = SQ * (1.f / DD) - mu * mu;
        mean_s = mu;
        rstd_s = rsqrtf(var + LN_EPS);
    }
    __syncthreads();
    float mu = mean_s, rs = rstd_s;
    float4 gv = *(const float4*)(g + c);
    float4 bv = *(const float4*)(b + c);
    float4 ov;
    ov.x = gv.x * (xv.x - mu) * rs + bv.x;
    ov.y = gv.y * (xv.y - mu) * rs + bv.y;
    ov.z = gv.z * (xv.z - mu) * rs + bv.z;
    ov.w = gv.w * (xv.w - mu) * rs + bv.w;
    *(float4*)(out + (size_t)row * DD + c) = ov;
}

// ---------------- SGEMM: C[M,Nc] = A[M,K] @ B[K,Nc] (+ Res) -----------------
// 128x128 block, BK=8, 256 threads, 8x8 per thread. All dims multiples of 128/8.
#define GBM 128
#define GBN 128
#define GBK 8
__global__ __launch_bounds__(256, 2)
void sgemm_kernel(const float* __restrict__ A, const float* __restrict__ B,
                  float* __restrict__ C, const float* __restrict__ Res,
                  int M, int Nc, int K) {
    __shared__ float As[GBK][GBM];
    __shared__ float Bs[GBK][GBN];
    int tid = threadIdx.x;
    int threadCol = tid & 15;   // 16 cols of 8
    int threadRow = tid >> 4;   // 16 rows of 8
    int aRow = tid >> 1;
    int aCol = (tid & 1) * 4;
    int bRow = tid >> 5;
    int bCol = (tid & 31) * 4;
    const float* Ab = A + (size_t)blockIdx.y * GBM * K;
    const float* Bb = B + (size_t)blockIdx.x * GBN;
    float acc[8][8];
    #pragma unroll
    for (int i = 0; i < 8; i++)
        #pragma unroll
        for (int j = 0; j < 8; j++) acc[i][j] = 0.f;
    float regM[8], regN[8];
    for (int k0 = 0; k0 < K; k0 += GBK) {
        float4 a4 = *(const float4*)(Ab + (size_t)aRow * K + k0 + aCol);
        As[aCol + 0][aRow] = a4.x;
        As[aCol + 1][aRow] = a4.y;
        As[aCol + 2][aRow] = a4.z;
        As[aCol + 3][aRow] = a4.w;
        *(float4*)(&Bs[bRow][bCol]) = *(const float4*)(Bb + (size_t)(k0 + bRow) * Nc + bCol);
        __syncthreads();
        #pragma unroll
        for (int k = 0; k < GBK; k++) {
            #pragma unroll
            for (int i = 0; i < 8; i++) regM[i] = As[k][threadRow * 8 + i];
            #pragma unroll
            for (int j = 0; j < 8; j++) regN[j] = Bs[k][threadCol * 8 + j];
            #pragma unroll
            for (int i = 0; i < 8; i++)
                #pragma unroll
                for (int j = 0; j < 8; j++) acc[i][j] += regM[i] * regN[j];
        }
        __syncthreads();
    }
    #pragma unroll
    for (int i = 0; i < 8; i++) {
        size_t row = (size_t)blockIdx.y * GBM + threadRow * 8 + i;
        #pragma unroll
        for (int j = 0; j < 8; j += 4) {
            size_t col = (size_t)blockIdx.x * GBN + threadCol * 8 + j;
            float4 v = make_float4(acc[i][j], acc[i][j+1], acc[i][j+2], acc[i][j+3]);
            if (Res) {
                float4 r = *(const float4*)(Res + row * Nc + col);
                v.x += r.x; v.y += r.y; v.z += r.z; v.w += r.w;
            }
            *(float4*)(C + row * Nc + col) = v;
        }
    }
}

// ---------------- combine: h[bs,r] = sum_n w[bs,n] * allh[bs, n*Rr + r] -----
__global__ void combine_kernel(const float* __restrict__ allh,
                               const float* __restrict__ w1, const float* __restrict__ w2,
                               float* __restrict__ h1, float* __restrict__ h2, int Rr) {
    int bs = blockIdx.x;
    int r = threadIdx.x;            // blockDim == Rr
    __shared__ float ws1[NN], ws2[NN];
    if (threadIdx.x < NN) {
        ws1[threadIdx.x] = w1[(size_t)bs * NN + threadIdx.x];
        if (w2) ws2[threadIdx.x] = w2[(size_t)bs * NN + threadIdx.x];
    }
    __syncthreads();
    const float* rowp = allh + (size_t)bs * NN * Rr;
    float a1 = 0.f, a2 = 0.f;
    #pragma unroll 8
    for (int n = 0; n < NN; n++) {
        float v = rowp[n * Rr + r];
        a1 += ws1[n] * v;
        if (w2) a2 += ws2[n] * v;
    }
    h1[(size_t)bs * Rr + r] = a1;
    if (w2) h2[(size_t)bs * Rr + r] = a2;
}

// ---------------- build T[bs, n*Rr + r] = w[bs,n] * h[bs,r] -----------------
__global__ void buildT_kernel(const float* __restrict__ h, const float* __restrict__ w,
                              float* __restrict__ T, int Rr) {
    int bs = blockIdx.x;
    __shared__ float hs[RKK];
    __shared__ float ws[NN];
    int tid = threadIdx.x;          // 256
    if (tid < Rr) hs[tid] = h[(size_t)bs * Rr + tid];
    if (tid < NN) ws[tid] = w[(size_t)bs * NN + tid];
    __syncthreads();
    int total = NN * Rr;
    float* Trow = T + (size_t)bs * total;
    for (int i = tid; i < total; i += 256) {
        int n = i / Rr;
        int r = i - n * Rr;
        Trow[i] = ws[n] * hs[r];
    }
}

// ---------------- flash attention, causal, fp32 -----------------------------
// grid (S/64, H, B), 256 threads; thread: q = tid>>2, quarter = tid&3
// thread owns cols {quarter + 4*k : k<16} of scores and of output dims
#define APAD 68
#define ATTN_SMEM (4 * 64 * APAD * 4)
__global__ void attn_kernel(const float* __restrict__ Q, const float* __restrict__ K,
                            const float* __restrict__ V, float* __restrict__ O) {
    extern __shared__ float sm[];
    float (*Qs)[APAD] = (float(*)[APAD])sm;
    float (*Ks)[APAD] = (float(*)[APAD])(sm + 64 * APAD);
    float (*Vs)[APAD] = (float(*)[APAD])(sm + 2 * 64 * APAD);
    float (*Ps)[APAD] = (float(*)[APAD])(sm + 3 * 64 * APAD);

    int qt = blockIdx.x, h = blockIdx.y, b = blockIdx.z;
    int tid = threadIdx.x;
    int q = tid >> 2;
    int quarter = tid & 3;
    const float scale = 0.125f;   // 1/sqrt(64)

    int s_q = qt * 64 + q;
    const float* Qrow = Q + ((size_t)(b * SS + s_q)) * DD + h * DHH;
    #pragma unroll
    for (int jj = 0; jj < 4; jj++) {
        int c = quarter * 16 + jj * 4;
        float4 v = *(const float4*)(Qrow + c);
        Qs[q][c]   = v.x * scale;
        Qs[q][c+1] = v.y * scale;
        Qs[q][c+2] = v.z * scale;
        Qs[q][c+3] = v.w * scale;
    }

    float m = -INFINITY, l = 0.f;
    float o[16];
    #pragma unroll
    for (int i = 0; i < 16; i++) o[i] = 0.f;

    int ntiles = qt + 1;
    for (int j = 0; j < ntiles; j++) {
        __syncthreads();
        {   // load K,V tiles (row per 4-thread group)
            const float* Krow = K + ((size_t)(b * SS + j * 64 + q)) * DD + h * DHH;
            const float* Vrow = V + ((size_t)(b * SS + j * 64 + q)) * DD + h * DHH;
            #pragma unroll
            for (int jj = 0; jj < 4; jj++) {
                int c = quarter * 16 + jj * 4;
                float4 kv = *(const float4*)(Krow + c);
                Ks[q][c] = kv.x; Ks[q][c+1] = kv.y; Ks[q][c+2] = kv.z; Ks[q][c+3] = kv.w;
                float4 vv = *(const float4*)(Vrow + c);
                Vs[q][c] = vv.x; Vs[q][c+1] = vv.y; Vs[q][c+2] = vv.z; Vs[q][c+3] = vv.w;
            }
        }
        __syncthreads();

        float s[16];
        #pragma unroll
        for (int kk = 0; kk < 16; kk++) s[kk] = 0.f;
        #pragma unroll 8
        for (int d = 0; d < 64; d++) {
            float qd = Qs[q][d];
            #pragma unroll
            for (int kk = 0; kk < 16; kk++)
                s[kk] += qd * Ks[quarter + 4 * kk][d];
        }
        if (j == qt) {
            #pragma unroll
            for (int kk = 0; kk < 16; kk++)
                if (quarter + 4 * kk > q) s[kk] = -INFINITY;
        }
        float mt = s[0];
        #pragma unroll
        for (int kk = 1; kk < 16; kk++) mt = fmaxf(mt, s[kk]);
        mt = fmaxf(mt, __shfl_xor_sync(0xffffffffu, mt, 1));
        mt = fmaxf(mt, __shfl_xor_sync(0xffffffffu, mt, 2));
        float mnew = fmaxf(m, mt);
        float lt = 0.f;
        #pragma unroll
        for (int kk = 0; kk < 16; kk++) {
            float p = __expf(s[kk] - mnew);
            lt += p;
            Ps[q][quarter + 4 * kk] = p;
        }
        lt += __shfl_xor_sync(0xffffffffu, lt, 1);
        lt += __shfl_xor_sync(0xffffffffu, lt, 2);
        float corr = __expf(m - mnew);
        l = l * corr + lt;
        m = mnew;
        #pragma unroll
        for (int i = 0; i < 16; i++) o[i] *= corr;
        __syncthreads();
        #pragma unroll 4
        for (int kc = 0; kc < 64; kc++) {
            float p = Ps[q][kc];
            #pragma unroll
            for (int dd = 0; dd < 16; dd++)
                o[dd] += p * Vs[kc][quarter + 4 * dd];
        }
    }
    float inv = 1.f / l;
    float* Orow = O + ((size_t)(b * SS + s_q)) * DD + h * DHH;
    #pragma unroll
    for (int dd = 0; dd < 16; dd++)
        Orow[quarter + 4 * dd] = o[dd] * inv;
}

// ---------------- launch -----------------------------------------------------
extern "C" void kernel_launch(void* const* d_in, const int* in_sizes, int n_in,
                              void* d_out, int out_size) {
    const float* x       = (const float*)d_in[0];
    const float* f_qk    = (const float*)d_in[1];
    const float* f_v     = (const float*)d_in[2];
    const float* r_qk    = (const float*)d_in[3];
    const float* r_v     = (const float*)d_in[4];
    const float* f_know  = (const float*)d_in[5];
    const float* r_know  = (const float*)d_in[6];
    const float* W_O     = (const float*)d_in[7];
    const float* gamma1  = (const float*)d_in[8];
    const float* beta1   = (const float*)d_in[9];
    const float* gamma2  = (const float*)d_in[10];
    const float* beta2   = (const float*)d_in[11];
    const float* w_fq    = (const float*)d_in[12];
    const float* w_fk    = (const float*)d_in[13];
    const float* w_fv    = (const float*)d_in[14];
    const float* w_rq    = (const float*)d_in[15];
    const float* w_rk    = (const float*)d_in[16];
    const float* w_rv    = (const float*)d_in[17];
    const float* w_know_f= (const float*)d_in[18];
    const float* w_know_r= (const float*)d_in[19];
    float* out = (float*)d_out;

    cudaFuncSetAttribute(attn_kernel, cudaFuncAttributeMaxDynamicSharedMemorySize, ATTN_SMEM);

    // device symbol addresses
    float *Bqk, *Bv, *Bkn, *WOT, *nx, *allh_qk, *allh_v, *allh_kn;
    float *hq, *hk, *hv, *hkn, *Tq, *Tk, *Tv, *Tkn, *Qd, *Kd, *Vd, *attn, *x1;
    cudaGetSymbolAddress((void**)&Bqk, g_Bqk);
    cudaGetSymbolAddress((void**)&Bv,  g_Bv);
    cudaGetSymbolAddress((void**)&Bkn, g_Bkn);
    cudaGetSymbolAddress((void**)&WOT, g_WOT);
    cudaGetSymbolAddress((void**)&nx,  g_nx);
    cudaGetSymbolAddress((void**)&allh_qk, g_allh_qk);
    cudaGetSymbolAddress((void**)&allh_v,  g_allh_v);
    cudaGetSymbolAddress((void**)&allh_kn, g_allh_kn);
    cudaGetSymbolAddress((void**)&hq, g_hq);
    cudaGetSymbolAddress((void**)&hk, g_hk);
    cudaGetSymbolAddress((void**)&hv, g_hv);
    cudaGetSymbolAddress((void**)&hkn, g_hkn);
    cudaGetSymbolAddress((void**)&Tq, g_Tq);
    cudaGetSymbolAddress((void**)&Tk, g_Tk);
    cudaGetSymbolAddress((void**)&Tv, g_Tv);
    cudaGetSymbolAddress((void**)&Tkn, g_Tkn);
    cudaGetSymbolAddress((void**)&Qd, g_Q);
    cudaGetSymbolAddress((void**)&Kd, g_K);
    cudaGetSymbolAddress((void**)&Vd, g_V);
    cudaGetSymbolAddress((void**)&attn, g_attn);
    cudaGetSymbolAddress((void**)&x1, g_x1);

    // pack neuron matrices + W_O^T
    pack_f_kernel<<<(DD*NN*RR + 255)/256, 256>>>(f_qk, Bqk, RR);
    pack_f_kernel<<<(DD*NN*RR + 255)/256, 256>>>(f_v,  Bv,  RR);
    pack_f_kernel<<<(DD*NN*RKK + 255)/256, 256>>>(f_know, Bkn, RKK);
    transpose_kernel<<<dim3(32,32), dim3(32,8)>>>(W_O, WOT);

    // --- attention circuit ---
    ln_kernel<<<BSZ, 256>>>(x, gamma1, beta1, nx);

    sgemm_kernel<<<dim3(NR/GBN, BSZ/GBM), 256>>>(nx, Bqk, allh_qk, nullptr, BSZ, NR, DD);
    sgemm_kernel<<<dim3(NR/GBN, BSZ/GBM), 256>>>(nx, Bv,  allh_v,  nullptr, BSZ, NR, DD);

    combine_kernel<<<BSZ, RR>>>(allh_qk, w_fq, w_fk, hq, hk, RR);
    combine_kernel<<<BSZ, RR>>>(allh_v,  w_fv, nullptr, hv, nullptr, RR);

    buildT_kernel<<<BSZ, 256>>>(hq, w_rq, Tq, RR);
    buildT_kernel<<<BSZ, 256>>>(hk, w_rk, Tk, RR);
    buildT_kernel<<<BSZ, 256>>>(hv, w_rv, Tv, RR);

    sgemm_kernel<<<dim3(DD/GBN, BSZ/GBM), 256>>>(Tq, r_qk, Qd, nullptr, BSZ, DD, NR);
    sgemm_kernel<<<dim3(DD/GBN, BSZ/GBM), 256>>>(Tk, r_qk, Kd, nullptr, BSZ, DD, NR);
    sgemm_kernel<<<dim3(DD/GBN, BSZ/GBM), 256>>>(Tv, r_v,  Vd, nullptr, BSZ, DD, NR);

    attn_kernel<<<dim3(SS/64, HH, BB), 256, ATTN_SMEM>>>(Qd, Kd, Vd, attn);

    // x1 = x + attn @ W_O^T
    sgemm_kernel<<<dim3(DD/GBN, BSZ/GBM), 256>>>(attn, WOT, x1, x, BSZ, DD, DD);

    // --- knowledge circuit ---
    ln_kernel<<<BSZ, 256>>>(x1, gamma2, beta2, nx);
    sgemm_kernel<<<dim3(NRK/GBN, BSZ/GBM), 256>>>(nx, Bkn, allh_kn, nullptr, BSZ, NRK, DD);
    combine_kernel<<<BSZ, RKK>>>(allh_kn, w_know_f, nullptr, hkn, nullptr, RKK);
    buildT_kernel<<<BSZ, 256>>>(hkn, w_know_r, Tkn, RKK);
    // out = x1 + Tkn @ r_know
    sgemm_kernel<<<dim3(DD/GBN, BSZ/GBM), 256>>>(Tkn, r_know, out, x1, BSZ, DD, NRK);
}

// round 4
// speedup vs baseline: 2.7194x; 2.7194x over previous
#include <cuda_runtime.h>
#include <cuda_bf16.h>
#include <math.h>
#include <stdint.h>

// Problem constants
#define BB 2
#define SS 2048
#define DD 1024
#define HH 16
#define RR 64
#define NN 32
#define RKK 128
#define DHH 64
#define BSZ (BB*SS)          // 4096 tokens
#define NR (NN*RR)           // 2048
#define NRK (NN*RKK)         // 4096
#define LN_EPS 1e-5f

typedef __nv_bfloat16 bf16;

// ---------------- scratch (static __device__; no allocations allowed) -------
__device__ bf16  g_Bqk[DD*NR];        // packed f_qk  [D, N*R]  (bf16)
__device__ bf16  g_Bv [DD*NR];        // packed f_v
__device__ bf16  g_Bkn[(size_t)DD*NRK];
__device__ bf16  g_WOT[DD*DD];        // W_O^T bf16
__device__ bf16  g_rqk[(size_t)NR*DD];
__device__ bf16  g_rv [(size_t)NR*DD];
__device__ bf16  g_rkn[(size_t)NRK*DD];
__device__ bf16  g_nx [BSZ*DD];       // LN output bf16 (reused for LN2)
__device__ float g_allh_qk[(size_t)BSZ*NR];
__device__ float g_allh_v [(size_t)BSZ*NR];
__device__ float g_allh_kn[(size_t)BSZ*NRK];
__device__ float g_hq[BSZ*RR], g_hk[BSZ*RR], g_hv[BSZ*RR], g_hkn[BSZ*RKK];
__device__ bf16  g_Tq[(size_t)BSZ*NR], g_Tk[(size_t)BSZ*NR], g_Tv[(size_t)BSZ*NR];
__device__ bf16  g_Tkn[(size_t)BSZ*NRK];
__device__ float g_Q[BSZ*DD], g_K[BSZ*DD], g_V[BSZ*DD];
__device__ bf16  g_attn[BSZ*DD];
__device__ float g_x1[BSZ*DD];

// ---------------- pack f[n,d,r] -> out[d, n*Rr + r]  (fp32 -> bf16) ---------
__global__ void pack_f_kernel(const float* __restrict__ in, bf16* __restrict__ out, int Rr) {
    int total = DD * NN * Rr;
    int idx = blockIdx.x * blockDim.x + threadIdx.x;
    if (idx >= total) return;
    int nr = NN * Rr;
    int d = idx / nr;
    int rem = idx - d * nr;
    int n = rem / Rr;
    int r = rem - n * Rr;
    out[idx] = __float2bfloat16(in[((size_t)n * DD + d) * Rr + r]);
}

// ---------------- fp32 -> bf16 elementwise ----------------------------------
__global__ void cvt_bf16_kernel(const float* __restrict__ in, bf16* __restrict__ out, int n) {
    int i = blockIdx.x * blockDim.x + threadIdx.x;
    if (i < n) out[i] = __float2bfloat16(in[i]);
}

// ---------------- transpose W_O -> W_O^T (bf16 out) -------------------------
__global__ void transpose_kernel(const float* __restrict__ in, bf16* __restrict__ out) {
    __shared__ float tile[32][33];
    int x = blockIdx.x * 32 + threadIdx.x;
    int y = blockIdx.y * 32 + threadIdx.y;
    #pragma unroll
    for (int i = 0; i < 32; i += 8)
        tile[threadIdx.y + i][threadIdx.x] = in[(size_t)(y + i) * DD + x];
    __syncthreads();
    x = blockIdx.y * 32 + threadIdx.x;
    y = blockIdx.x * 32 + threadIdx.y;
    #pragma unroll
    for (int i = 0; i < 32; i += 8)
        out[(size_t)(y + i) * DD + x] = __float2bfloat16(tile[threadIdx.x][threadIdx.y + i]);
}

// ---------------- LayerNorm: one block (256 thr) per row of 1024, bf16 out --
__global__ void ln_kernel(const float* __restrict__ x, const float* __restrict__ g,
                          const float* __restrict__ b, bf16* __restrict__ out) {
    int row = blockIdx.x;
    const float* xr = x + (size_t)row * DD;
    int c = threadIdx.x * 4;
    float4 xv = *(const float4*)(xr + c);
    float s  = xv.x + xv.y + xv.z + xv.w;
    float sq = xv.x*xv.x + xv.y*xv.y + xv.z*xv.z + xv.w*xv.w;
    #pragma unroll
    for (int o = 16; o > 0; o >>= 1) {
        s  += __shfl_xor_sync(0xffffffffu, s,  o);
        sq += __shfl_xor_sync(0xffffffffu, sq, o);
    }
    __shared__ float ss[8], ssq[8];
    __shared__ float mean_s, rstd_s;
    int wid = threadIdx.x >> 5, lid = threadIdx.x & 31;
    if (lid == 0) { ss[wid] = s; ssq[wid] = sq; }
    __syncthreads();
    if (threadIdx.x == 0) {
        float S = 0.f, SQ = 0.f;
        #pragma unroll
        for (int i = 0; i < 8; i++) { S += ss[i]; SQ += ssq[i]; }
        float mu  = S * (1.f / DD);
        float var = SQ * (1.f / DD) - mu * mu;
        mean_s = mu;
        rstd_s = rsqrtf(var + LN_EPS);
    }
    __syncthreads();
    float mu = mean_s, rs = rstd_s;
    float4 gv = *(const float4*)(g + c);
    float4 bv = *(const float4*)(b + c);
    bf16* orow = out + (size_t)row * DD + c;
    orow[0] = __float2bfloat16(gv.x * (xv.x - mu) * rs + bv.x);
    orow[1] = __float2bfloat16(gv.y * (xv.y - mu) * rs + bv.y);
    orow[2] = __float2bfloat16(gv.z * (xv.z - mu) * rs + bv.z);
    orow[3] = __float2bfloat16(gv.w * (xv.w - mu) * rs + bv.w);
}

// ================== bf16 tensor-core GEMM ====================================
// C[M,Nc] (fp32, + optional fp32 Res) = A[M,K](bf16,row) @ B[K,Nc](bf16,row)
// CTA 128x128x32, 8 warps (2 along M x 4 along N), warp tile 64x32,
// mma.m16n8k16, cp.async double buffer, ldmatrix (.trans for B).
#define TM 128
#define TN 128
#define TK 32
#define ASTR 40     // padded row stride (bf16 elems) for A tile -> conflict-free ldmatrix
#define BSTR 136    // padded row stride for B tile

__device__ __forceinline__ uint32_t smem_u32(const void* p) {
    return (uint32_t)__cvta_generic_to_shared(p);
}
__device__ __forceinline__ void cp16(uint32_t saddr, const void* gaddr) {
    asm volatile("cp.async.cg.shared.global [%0], [%1], 16;\n" :: "r"(saddr), "l"(gaddr));
}
__device__ __forceinline__ void cp_commit() { asm volatile("cp.async.commit_group;\n"); }
template<int N> __device__ __forceinline__ void cp_wait() {
    asm volatile("cp.async.wait_group %0;\n" :: "n"(N));
}
__device__ __forceinline__ void ldsm_x4(uint32_t& r0, uint32_t& r1, uint32_t& r2, uint32_t& r3, uint32_t addr) {
    asm volatile("ldmatrix.sync.aligned.m8n8.x4.shared.b16 {%0,%1,%2,%3}, [%4];\n"
                 : "=r"(r0), "=r"(r1), "=r"(r2), "=r"(r3) : "r"(addr));
}
__device__ __forceinline__ void ldsm_x4_t(uint32_t& r0, uint32_t& r1, uint32_t& r2, uint32_t& r3, uint32_t addr) {
    asm volatile("ldmatrix.sync.aligned.m8n8.x4.trans.shared.b16 {%0,%1,%2,%3}, [%4];\n"
                 : "=r"(r0), "=r"(r1), "=r"(r2), "=r"(r3) : "r"(addr));
}
__device__ __forceinline__ void mma16816(float* d, const uint32_t* a, const uint32_t* b) {
    asm volatile("mma.sync.aligned.m16n8k16.row.col.f32.bf16.bf16.f32 "
                 "{%0,%1,%2,%3}, {%4,%5,%6,%7}, {%8,%9}, {%0,%1,%2,%3};\n"
                 : "+f"(d[0]), "+f"(d[1]), "+f"(d[2]), "+f"(d[3])
                 : "r"(a[0]), "r"(a[1]), "r"(a[2]), "r"(a[3]), "r"(b[0]), "r"(b[1]));
}

__global__ __launch_bounds__(256, 2)
void hgemm_kernel(const bf16* __restrict__ A, const bf16* __restrict__ B,
                  float* __restrict__ C, const float* __restrict__ Res,
                  int M, int Nc, int K) {
    __shared__ bf16 As[2][TM][ASTR];
    __shared__ bf16 Bs[2][TK][BSTR];
    int tid = threadIdx.x;
    int lane = tid & 31;
    int warp = tid >> 5;
    int warp_m = warp & 1;      // 0..1 (64 rows each)
    int warp_n = warp >> 1;     // 0..3 (32 cols each)

    const bf16* Ab = A + (size_t)blockIdx.y * TM * K;
    const bf16* Bb = B + (size_t)blockIdx.x * TN;

    float acc[4][4][4];
    #pragma unroll
    for (int i = 0; i < 4; i++)
        #pragma unroll
        for (int j = 0; j < 4; j++)
            #pragma unroll
            for (int v = 0; v < 4; v++) acc[i][j][v] = 0.f;

    // load mapping
    int a_row = tid >> 1;            // 0..127
    int a_c0  = (tid & 1) * 16;      // 0 or 16
    int b_row = tid >> 4;            // 0..15  (2 rows/thread, +16 below)
    int b_c0  = (tid & 15) * 8;      // 0..120

    // prologue: stage 0
    {
        uint32_t sa = smem_u32(&As[0][a_row][a_c0]);
        cp16(sa,      Ab + (size_t)a_row * K + a_c0);
        cp16(sa + 16, Ab + (size_t)a_row * K + a_c0 + 8);
        uint32_t sb0 = smem_u32(&Bs[0][b_row][b_c0]);
        uint32_t sb1 = smem_u32(&Bs[0][b_row + 16][b_c0]);
        cp16(sb0, Bb + (size_t)b_row * Nc + b_c0);
        cp16(sb1, Bb + (size_t)(b_row + 16) * Nc + b_c0);
    }
    cp_commit();

    int KT = K / TK;
    for (int kt = 0; kt < KT; kt++) {
        if (kt + 1 < KT) {
            int st = (kt + 1) & 1;
            int k0 = (kt + 1) * TK;
            uint32_t sa = smem_u32(&As[st][a_row][a_c0]);
            cp16(sa,      Ab + (size_t)a_row * K + k0 + a_c0);
            cp16(sa + 16, Ab + (size_t)a_row * K + k0 + a_c0 + 8);
            uint32_t sb0 = smem_u32(&Bs[st][b_row][b_c0]);
            uint32_t sb1 = smem_u32(&Bs[st][b_row + 16][b_c0]);
            cp16(sb0, Bb + (size_t)(k0 + b_row) * Nc + b_c0);
            cp16(sb1, Bb + (size_t)(k0 + b_row + 16) * Nc + b_c0);
            cp_commit();
            cp_wait<1>();
        } else {
            cp_wait<0>();
        }
        __syncthreads();
        int st = kt & 1;
        #pragma unroll
        for (int kk = 0; kk < TK; kk += 16) {
            uint32_t af[4][4];
            #pragma unroll
            for (int i = 0; i < 4; i++) {
                int row = warp_m * 64 + i * 16 + (lane & 15);
                int col = kk + (lane >> 4) * 8;
                ldsm_x4(af[i][0], af[i][1], af[i][2], af[i][3], smem_u32(&As[st][row][col]));
            }
            uint32_t bf[4][2];
            #pragma unroll
            for (int jp = 0; jp < 2; jp++) {
                int n0 = warp_n * 32 + jp * 16;
                int kr = kk + (lane & 7) + ((lane & 16) ? 8 : 0);
                int col = n0 + ((lane >> 3) & 1) * 8;
                uint32_t r0, r1, r2, r3;
                ldsm_x4_t(r0, r1, r2, r3, smem_u32(&Bs[st][kr][col]));
                bf[jp*2][0] = r0; bf[jp*2+1][0] = r1;
                bf[jp*2][1] = r2; bf[jp*2+1][1] = r3;
            }
            #pragma unroll
            for (int i = 0; i < 4; i++)
                #pragma unroll
                for (int j = 0; j < 4; j++)
                    mma16816(acc[i][j], af[i], bf[j]);
        }
        __syncthreads();
    }

    // epilogue
    size_t blockRow = (size_t)blockIdx.y * TM;
    size_t blockCol = (size_t)blockIdx.x * TN;
    #pragma unroll
    for (int i = 0; i < 4; i++) {
        size_t r0 = blockRow + warp_m * 64 + i * 16 + (lane >> 2);
        #pragma unroll
        for (int j = 0; j < 4; j++) {
            size_t c0 = blockCol + warp_n * 32 + j * 8 + (lane & 3) * 2;
            float2 v0 = make_float2(acc[i][j][0], acc[i][j][1]);
            float2 v1 = make_float2(acc[i][j][2], acc[i][j][3]);
            if (Res) {
                const float2 q0 = *(const float2*)(Res + r0 * Nc + c0);
                const float2 q1 = *(const float2*)(Res + (r0 + 8) * Nc + c0);
                v0.x += q0.x; v0.y += q0.y; v1.x += q1.x; v1.y += q1.y;
            }
            *(float2*)(C + r0 * Nc + c0) = v0;
            *(float2*)(C + (r0 + 8) * Nc + c0) = v1;
        }
    }
}

// ---------------- combine: h[bs,r] = sum_n w[bs,n] * allh[bs, n*Rr + r] -----
__global__ void combine_kernel(const float* __restrict__ allh,
                               const float* __restrict__ w1, const float* __restrict__ w2,
                               float* __restrict__ h1, float* __restrict__ h2, int Rr) {
    int bs = blockIdx.x;
    int r = threadIdx.x;            // blockDim == Rr
    __shared__ float ws1[NN], ws2[NN];
    if (threadIdx.x < NN) {
        ws1[threadIdx.x] = w1[(size_t)bs * NN + threadIdx.x];
        if (w2) ws2[threadIdx.x] = w2[(size_t)bs * NN + threadIdx.x];
    }
    __syncthreads();
    const float* rowp = allh + (size_t)bs * NN * Rr;
    float a1 = 0.f, a2 = 0.f;
    #pragma unroll 8
    for (int n = 0; n < NN; n++) {
        float v = rowp[n * Rr + r];
        a1 += ws1[n] * v;
        if (w2) a2 += ws2[n] * v;
    }
    h1[(size_t)bs * Rr + r] = a1;
    if (w2) h2[(size_t)bs * Rr + r] = a2;
}

// ---------------- build T[bs, n*Rr + r] = w[bs,n] * h[bs,r]  (bf16 out) -----
__global__ void buildT_kernel(const float* __restrict__ h, const float* __restrict__ w,
                              bf16* __restrict__ T, int Rr) {
    int bs = blockIdx.x;
    __shared__ float hs[RKK];
    __shared__ float ws[NN];
    int tid = threadIdx.x;          // 256
    if (tid < Rr) hs[tid] = h[(size_t)bs * Rr + tid];
    if (tid < NN) ws[tid] = w[(size_t)bs * NN + tid];
    __syncthreads();
    int total = NN * Rr;
    bf16* Trow = T + (size_t)bs * total;
    for (int i = tid; i < total; i += 256) {
        int n = i / Rr;
        int r = i - n * Rr;
        Trow[i] = __float2bfloat16(ws[n] * hs[r]);
    }
}

// ---------------- flash attention, causal, fp32 (bf16 output) ---------------
#define APAD 68
#define ATTN_SMEM (4 * 64 * APAD * 4)
__global__ void attn_kernel(const float* __restrict__ Q, const float* __restrict__ K,
                            const float* __restrict__ V, bf16* __restrict__ O) {
    extern __shared__ float sm[];
    float (*Qs)[APAD] = (float(*)[APAD])sm;
    float (*Ks)[APAD] = (float(*)[APAD])(sm + 64 * APAD);
    float (*Vs)[APAD] = (float(*)[APAD])(sm + 2 * 64 * APAD);
    float (*Ps)[APAD] = (float(*)[APAD])(sm + 3 * 64 * APAD);

    int qt = blockIdx.x, h = blockIdx.y, b = blockIdx.z;
    int tid = threadIdx.x;
    int q = tid >> 2;
    int quarter = tid & 3;
    const float scale = 0.125f;   // 1/sqrt(64)

    int s_q = qt * 64 + q;
    const float* Qrow = Q + ((size_t)(b * SS + s_q)) * DD + h * DHH;
    #pragma unroll
    for (int jj = 0; jj < 4; jj++) {
        int c = quarter * 16 + jj * 4;
        float4 v = *(const float4*)(Qrow + c);
        Qs[q][c]   = v.x * scale;
        Qs[q][c+1] = v.y * scale;
        Qs[q][c+2] = v.z * scale;
        Qs[q][c+3] = v.w * scale;
    }

    float m = -INFINITY, l = 0.f;
    float o[16];
    #pragma unroll
    for (int i = 0; i < 16; i++) o[i] = 0.f;

    int ntiles = qt + 1;
    for (int j = 0; j < ntiles; j++) {
        __syncthreads();
        {
            const float* Krow = K + ((size_t)(b * SS + j * 64 + q)) * DD + h * DHH;
            const float* Vrow = V + ((size_t)(b * SS + j * 64 + q)) * DD + h * DHH;
            #pragma unroll
            for (int jj = 0; jj < 4; jj++) {
                int c = quarter * 16 + jj * 4;
                float4 kv = *(const float4*)(Krow + c);
                Ks[q][c] = kv.x; Ks[q][c+1] = kv.y; Ks[q][c+2] = kv.z; Ks[q][c+3] = kv.w;
                float4 vv = *(const float4*)(Vrow + c);
                Vs[q][c] = vv.x; Vs[q][c+1] = vv.y; Vs[q][c+2] = vv.z; Vs[q][c+3] = vv.w;
            }
        }
        __syncthreads();

        float s[16];
        #pragma unroll
        for (int kk = 0; kk < 16; kk++) s[kk] = 0.f;
        #pragma unroll 8
        for (int d = 0; d < 64; d++) {
            float qd = Qs[q][d];
            #pragma unroll
            for (int kk = 0; kk < 16; kk++)
                s[kk] += qd * Ks[quarter + 4 * kk][d];
        }
        if (j == qt) {
            #pragma unroll
            for (int kk = 0; kk < 16; kk++)
                if (quarter + 4 * kk > q) s[kk] = -INFINITY;
        }
        float mt = s[0];
        #pragma unroll
        for (int kk = 1; kk < 16; kk++) mt = fmaxf(mt, s[kk]);
        mt = fmaxf(mt, __shfl_xor_sync(0xffffffffu, mt, 1));
        mt = fmaxf(mt, __shfl_xor_sync(0xffffffffu, mt, 2));
        float mnew = fmaxf(m, mt);
        float lt = 0.f;
        #pragma unroll
        for (int kk = 0; kk < 16; kk++) {
            float p = __expf(s[kk] - mnew);
            lt += p;
            Ps[q][quarter + 4 * kk] = p;
        }
        lt += __shfl_xor_sync(0xffffffffu, lt, 1);
        lt += __shfl_xor_sync(0xffffffffu, lt, 2);
        float corr = __expf(m - mnew);
        l = l * corr + lt;
        m = mnew;
        #pragma unroll
        for (int i = 0; i < 16; i++) o[i] *= corr;
        __syncthreads();
        #pragma unroll 4
        for (int kc = 0; kc < 64; kc++) {
            float p = Ps[q][kc];
            #pragma unroll
            for (int dd = 0; dd < 16; dd++)
                o[dd] += p * Vs[kc][quarter + 4 * dd];
        }
    }
    float inv = 1.f / l;
    bf16* Orow = O + ((size_t)(b * SS + s_q)) * DD + h * DHH;
    #pragma unroll
    for (int dd = 0; dd < 16; dd++)
        Orow[quarter + 4 * dd] = __float2bfloat16(o[dd] * inv);
}

// ---------------- launch -----------------------------------------------------
extern "C" void kernel_launch(void* const* d_in, const int* in_sizes, int n_in,
                              void* d_out, int out_size) {
    const float* x       = (const float*)d_in[0];
    const float* f_qk    = (const float*)d_in[1];
    const float* f_v     = (const float*)d_in[2];
    const float* r_qk    = (const float*)d_in[3];
    const float* r_v     = (const float*)d_in[4];
    const float* f_know  = (const float*)d_in[5];
    const float* r_know  = (const float*)d_in[6];
    const float* W_O     = (const float*)d_in[7];
    const float* gamma1  = (const float*)d_in[8];
    const float* beta1   = (const float*)d_in[9];
    const float* gamma2  = (const float*)d_in[10];
    const float* beta2   = (const float*)d_in[11];
    const float* w_fq    = (const float*)d_in[12];
    const float* w_fk    = (const float*)d_in[13];
    const float* w_fv    = (const float*)d_in[14];
    const float* w_rq    = (const float*)d_in[15];
    const float* w_rk    = (const float*)d_in[16];
    const float* w_rv    = (const float*)d_in[17];
    const float* w_know_f= (const float*)d_in[18];
    const float* w_know_r= (const float*)d_in[19];
    float* out = (float*)d_out;

    cudaFuncSetAttribute(attn_kernel, cudaFuncAttributeMaxDynamicSharedMemorySize, ATTN_SMEM);

    bf16 *Bqk, *Bv, *Bkn, *WOT, *nx, *rqk, *rv, *rkn, *Tq, *Tk, *Tv, *Tkn, *attn;
    float *allh_qk, *allh_v, *allh_kn, *hq, *hk, *hv, *hkn, *Qd, *Kd, *Vd, *x1;
    cudaGetSymbolAddress((void**)&Bqk, g_Bqk);
    cudaGetSymbolAddress((void**)&Bv,  g_Bv);
    cudaGetSymbolAddress((void**)&Bkn, g_Bkn);
    cudaGetSymbolAddress((void**)&WOT, g_WOT);
    cudaGetSymbolAddress((void**)&rqk, g_rqk);
    cudaGetSymbolAddress((void**)&rv,  g_rv);
    cudaGetSymbolAddress((void**)&rkn, g_rkn);
    cudaGetSymbolAddress((void**)&nx,  g_nx);
    cudaGetSymbolAddress((void**)&allh_qk, g_allh_qk);
    cudaGetSymbolAddress((void**)&allh_v,  g_allh_v);
    cudaGetSymbolAddress((void**)&allh_kn, g_allh_kn);
    cudaGetSymbolAddress((void**)&hq, g_hq);
    cudaGetSymbolAddress((void**)&hk, g_hk);
    cudaGetSymbolAddress((void**)&hv, g_hv);
    cudaGetSymbolAddress((void**)&hkn, g_hkn);
    cudaGetSymbolAddress((void**)&Tq, g_Tq);
    cudaGetSymbolAddress((void**)&Tk, g_Tk);
    cudaGetSymbolAddress((void**)&Tv, g_Tv);
    cudaGetSymbolAddress((void**)&Tkn, g_Tkn);
    cudaGetSymbolAddress((void**)&Qd, g_Q);
    cudaGetSymbolAddress((void**)&Kd, g_K);
    cudaGetSymbolAddress((void**)&Vd, g_V);
    cudaGetSymbolAddress((void**)&attn, g_attn);
    cudaGetSymbolAddress((void**)&x1, g_x1);

    // pack neuron matrices (bf16) + W_O^T + restore-matrix conversions
    pack_f_kernel<<<(DD*NN*RR + 255)/256, 256>>>(f_qk, Bqk, RR);
    pack_f_kernel<<<(DD*NN*RR + 255)/256, 256>>>(f_v,  Bv,  RR);
    pack_f_kernel<<<(DD*NN*RKK + 255)/256, 256>>>(f_know, Bkn, RKK);
    transpose_kernel<<<dim3(32,32), dim3(32,8)>>>(W_O, WOT);
    cvt_bf16_kernel<<<(NR*DD + 255)/256, 256>>>(r_qk, rqk, NR*DD);
    cvt_bf16_kernel<<<(NR*DD + 255)/256, 256>>>(r_v,  rv,  NR*DD);
    cvt_bf16_kernel<<<(NRK*DD + 255)/256, 256>>>(r_know, rkn, NRK*DD);

    // --- attention circuit ---
    ln_kernel<<<BSZ, 256>>>(x, gamma1, beta1, nx);

    hgemm_kernel<<<dim3(NR/TN, BSZ/TM), 256>>>(nx, Bqk, allh_qk, nullptr, BSZ, NR, DD);
    hgemm_kernel<<<dim3(NR/TN, BSZ/TM), 256>>>(nx, Bv,  allh_v,  nullptr, BSZ, NR, DD);

    combine_kernel<<<BSZ, RR>>>(allh_qk, w_fq, w_fk, hq, hk, RR);
    combine_kernel<<<BSZ, RR>>>(allh_v,  w_fv, nullptr, hv, nullptr, RR);

    buildT_kernel<<<BSZ, 256>>>(hq, w_rq, Tq, RR);
    buildT_kernel<<<BSZ, 256>>>(hk, w_rk, Tk, RR);
    buildT_kernel<<<BSZ, 256>>>(hv, w_rv, Tv, RR);

    hgemm_kernel<<<dim3(DD/TN, BSZ/TM), 256>>>(Tq, rqk, Qd, nullptr, BSZ, DD, NR);
    hgemm_kernel<<<dim3(DD/TN, BSZ/TM), 256>>>(Tk, rqk, Kd, nullptr, BSZ, DD, NR);
    hgemm_kernel<<<dim3(DD/TN, BSZ/TM), 256>>>(Tv, rv,  Vd, nullptr, BSZ, DD, NR);

    attn_kernel<<<dim3(SS/64, HH, BB), 256, ATTN_SMEM>>>(Qd, Kd, Vd, attn);

    // x1 = x + attn @ W_O^T
    hgemm_kernel<<<dim3(DD/TN, BSZ/TM), 256>>>(attn, WOT, x1, x, BSZ, DD, DD);

    // --- knowledge circuit ---
    ln_kernel<<<BSZ, 256>>>(x1, gamma2, beta2, nx);
    hgemm_kernel<<<dim3(NRK/TN, BSZ/TM), 256>>>(nx, Bkn, allh_kn, nullptr, BSZ, NRK, DD);
    combine_kernel<<<BSZ, RKK>>>(allh_kn, w_know_f, nullptr, hkn, nullptr, RKK);
    buildT_kernel<<<BSZ, 256>>>(hkn, w_know_r, Tkn, RKK);
    // out = x1 + Tkn @ r_know
    hgemm_kernel<<<dim3(DD/TN, BSZ/TM), 256>>>(Tkn, rkn, out, x1, BSZ, DD, NRK);
}

// round 6
// speedup vs baseline: 6.2550x; 2.3001x over previous
#include <cuda_runtime.h>
#include <cuda_bf16.h>
#include <math.h>
#include <stdint.h>

// Problem constants
#define BB 2
#define SS 2048
#define DD 1024
#define HH 16
#define RR 64
#define NN 32
#define RKK 128
#define DHH 64
#define BSZ (BB*SS)          // 4096 tokens
#define NR (NN*RR)           // 2048
#define NRK (NN*RKK)         // 4096
#define LN_EPS 1e-5f

typedef __nv_bfloat16 bf16;

// ---------------- scratch (static __device__; no allocations allowed) -------
__device__ bf16  g_Bqk[DD*NR];
__device__ bf16  g_Bv [DD*NR];
__device__ bf16  g_Bkn[(size_t)DD*NRK];
__device__ bf16  g_WOT[DD*DD];
__device__ bf16  g_rqk[(size_t)NR*DD];
__device__ bf16  g_rv [(size_t)NR*DD];
__device__ bf16  g_rkn[(size_t)NRK*DD];
__device__ bf16  g_nx [BSZ*DD];
__device__ float g_allh_qk[(size_t)BSZ*NR];
__device__ float g_allh_v [(size_t)BSZ*NR];
__device__ float g_allh_kn[(size_t)BSZ*NRK];
__device__ float g_hq[BSZ*RR], g_hk[BSZ*RR], g_hv[BSZ*RR], g_hkn[BSZ*RKK];
__device__ bf16  g_Tq[(size_t)BSZ*NR], g_Tk[(size_t)BSZ*NR], g_Tv[(size_t)BSZ*NR];
__device__ bf16  g_Tkn[(size_t)BSZ*NRK];
__device__ bf16  g_Qb[BSZ*DD], g_Kb[BSZ*DD], g_Vb[BSZ*DD];   // bf16 Q,K,V
__device__ bf16  g_attn[BSZ*DD];
__device__ float g_x1[BSZ*DD];

// ---------------- helpers ---------------------------------------------------
__device__ __forceinline__ uint32_t smem_u32(const void* p) {
    return (uint32_t)__cvta_generic_to_shared(p);
}
__device__ __forceinline__ void cp16(uint32_t saddr, const void* gaddr) {
    asm volatile("cp.async.cg.shared.global [%0], [%1], 16;\n" :: "r"(saddr), "l"(gaddr));
}
__device__ __forceinline__ void cp_commit() { asm volatile("cp.async.commit_group;\n"); }
template<int N> __device__ __forceinline__ void cp_wait() {
    asm volatile("cp.async.wait_group %0;\n" :: "n"(N));
}
__device__ __forceinline__ void ldsm_x4(uint32_t& r0, uint32_t& r1, uint32_t& r2, uint32_t& r3, uint32_t addr) {
    asm volatile("ldmatrix.sync.aligned.m8n8.x4.shared.b16 {%0,%1,%2,%3}, [%4];\n"
                 : "=r"(r0), "=r"(r1), "=r"(r2), "=r"(r3) : "r"(addr));
}
__device__ __forceinline__ void ldsm_x4_t(uint32_t& r0, uint32_t& r1, uint32_t& r2, uint32_t& r3, uint32_t addr) {
    asm volatile("ldmatrix.sync.aligned.m8n8.x4.trans.shared.b16 {%0,%1,%2,%3}, [%4];\n"
                 : "=r"(r0), "=r"(r1), "=r"(r2), "=r"(r3) : "r"(addr));
}
__device__ __forceinline__ void mma16816(float* d, const uint32_t* a, const uint32_t* b) {
    asm volatile("mma.sync.aligned.m16n8k16.row.col.f32.bf16.bf16.f32 "
                 "{%0,%1,%2,%3}, {%4,%5,%6,%7}, {%8,%9}, {%0,%1,%2,%3};\n"
                 : "+f"(d[0]), "+f"(d[1]), "+f"(d[2]), "+f"(d[3])
                 : "r"(a[0]), "r"(a[1]), "r"(a[2]), "r"(a[3]), "r"(b[0]), "r"(b[1]));
}
__device__ __forceinline__ uint32_t pack_bf16(float x, float y) {
    __nv_bfloat162 t = __floats2bfloat162_rn(x, y);
    return *(uint32_t*)&t;
}

// ---------------- pack f[n,d,r] -> out[d, n*Rr + r]  (fp32 -> bf16) ---------
__global__ void pack_f_kernel(const float* __restrict__ in, bf16* __restrict__ out, int Rr) {
    int total = DD * NN * Rr;
    int idx = blockIdx.x * blockDim.x + threadIdx.x;
    if (idx >= total) return;
    int nr = NN * Rr;
    int d = idx / nr;
    int rem = idx - d * nr;
    int n = rem / Rr;
    int r = rem - n * Rr;
    out[idx] = __float2bfloat16(in[((size_t)n * DD + d) * Rr + r]);
}

__global__ void cvt_bf16_kernel(const float* __restrict__ in, bf16* __restrict__ out, int n) {
    int i = blockIdx.x * blockDim.x + threadIdx.x;
    if (i < n) out[i] = __float2bfloat16(in[i]);
}

__global__ void transpose_kernel(const float* __restrict__ in, bf16* __restrict__ out) {
    __shared__ float tile[32][33];
    int x = blockIdx.x * 32 + threadIdx.x;
    int y = blockIdx.y * 32 + threadIdx.y;
    #pragma unroll
    for (int i = 0; i < 32; i += 8)
        tile[threadIdx.y + i][threadIdx.x] = in[(size_t)(y + i) * DD + x];
    __syncthreads();
    x = blockIdx.y * 32 + threadIdx.x;
    y = blockIdx.x * 32 + threadIdx.y;
    #pragma unroll
    for (int i = 0; i < 32; i += 8)
        out[(size_t)(y + i) * DD + x] = __float2bfloat16(tile[threadIdx.x][threadIdx.y + i]);
}

// ---------------- LayerNorm -------------------------------------------------
__global__ void ln_kernel(const float* __restrict__ x, const float* __restrict__ g,
                          const float* __restrict__ b, bf16* __restrict__ out) {
    int row = blockIdx.x;
    const float* xr = x + (size_t)row * DD;
    int c = threadIdx.x * 4;
    float4 xv = *(const float4*)(xr + c);
    float s  = xv.x + xv.y + xv.z + xv.w;
    float sq = xv.x*xv.x + xv.y*xv.y + xv.z*xv.z + xv.w*xv.w;
    #pragma unroll
    for (int o = 16; o > 0; o >>= 1) {
        s  += __shfl_xor_sync(0xffffffffu, s,  o);
        sq += __shfl_xor_sync(0xffffffffu, sq, o);
    }
    __shared__ float ss[8], ssq[8];
    __shared__ float mean_s, rstd_s;
    int wid = threadIdx.x >> 5, lid = threadIdx.x & 31;
    if (lid == 0) { ss[wid] = s; ssq[wid] = sq; }
    __syncthreads();
    if (threadIdx.x == 0) {
        float S = 0.f, SQ = 0.f;
        #pragma unroll
        for (int i = 0; i < 8; i++) { S += ss[i]; SQ += ssq[i]; }
        float mu  = S * (1.f / DD);
        float var = SQ * (1.f / DD) - mu * mu;
        mean_s = mu;
        rstd_s = rsqrtf(var + LN_EPS);
    }
    __syncthreads();
    float mu = mean_s, rs = rstd_s;
    float4 gv = *(const float4*)(g + c);
    float4 bv = *(const float4*)(b + c);
    bf16* orow = out + (size_t)row * DD + c;
    orow[0] = __float2bfloat16(gv.x * (xv.x - mu) * rs + bv.x);
    orow[1] = __float2bfloat16(gv.y * (xv.y - mu) * rs + bv.y);
    orow[2] = __float2bfloat16(gv.z * (xv.z - mu) * rs + bv.z);
    orow[3] = __float2bfloat16(gv.w * (xv.w - mu) * rs + bv.w);
}

// ================== bf16 tensor-core GEMM (fp32 or bf16 out) =================
#define TM 128
#define TN 128
#define TK 32
#define ASTR 40
#define BSTR 136

template<typename OutT>
__global__ __launch_bounds__(256, 2)
void hgemm_kernel(const bf16* __restrict__ A, const bf16* __restrict__ B,
                  OutT* __restrict__ C, const float* __restrict__ Res,
                  int M, int Nc, int K) {
    __shared__ bf16 As[2][TM][ASTR];
    __shared__ bf16 Bs[2][TK][BSTR];
    int tid = threadIdx.x;
    int lane = tid & 31;
    int warp = tid >> 5;
    int warp_m = warp & 1;
    int warp_n = warp >> 1;

    const bf16* Ab = A + (size_t)blockIdx.y * TM * K;
    const bf16* Bb = B + (size_t)blockIdx.x * TN;

    float acc[4][4][4];
    #pragma unroll
    for (int i = 0; i < 4; i++)
        #pragma unroll
        for (int j = 0; j < 4; j++)
            #pragma unroll
            for (int v = 0; v < 4; v++) acc[i][j][v] = 0.f;

    int a_row = tid >> 1;
    int a_c0  = (tid & 1) * 16;
    int b_row = tid >> 4;
    int b_c0  = (tid & 15) * 8;

    {
        uint32_t sa = smem_u32(&As[0][a_row][a_c0]);
        cp16(sa,      Ab + (size_t)a_row * K + a_c0);
        cp16(sa + 16, Ab + (size_t)a_row * K + a_c0 + 8);
        uint32_t sb0 = smem_u32(&Bs[0][b_row][b_c0]);
        uint32_t sb1 = smem_u32(&Bs[0][b_row + 16][b_c0]);
        cp16(sb0, Bb + (size_t)b_row * Nc + b_c0);
        cp16(sb1, Bb + (size_t)(b_row + 16) * Nc + b_c0);
    }
    cp_commit();

    int KT = K / TK;
    for (int kt = 0; kt < KT; kt++) {
        if (kt + 1 < KT) {
            int st = (kt + 1) & 1;
            int k0 = (kt + 1) * TK;
            uint32_t sa = smem_u32(&As[st][a_row][a_c0]);
            cp16(sa,      Ab + (size_t)a_row * K + k0 + a_c0);
            cp16(sa + 16, Ab + (size_t)a_row * K + k0 + a_c0 + 8);
            uint32_t sb0 = smem_u32(&Bs[st][b_row][b_c0]);
            uint32_t sb1 = smem_u32(&Bs[st][b_row + 16][b_c0]);
            cp16(sb0, Bb + (size_t)(k0 + b_row) * Nc + b_c0);
            cp16(sb1, Bb + (size_t)(k0 + b_row + 16) * Nc + b_c0);
            cp_commit();
            cp_wait<1>();
        } else {
            cp_wait<0>();
        }
        __syncthreads();
        int st = kt & 1;
        #pragma unroll
        for (int kk = 0; kk < TK; kk += 16) {
            uint32_t af[4][4];
            #pragma unroll
            for (int i = 0; i < 4; i++) {
                int row = warp_m * 64 + i * 16 + (lane & 15);
                int col = kk + (lane >> 4) * 8;
                ldsm_x4(af[i][0], af[i][1], af[i][2], af[i][3], smem_u32(&As[st][row][col]));
            }
            uint32_t bfr[4][2];
            #pragma unroll
            for (int jp = 0; jp < 2; jp++) {
                int n0 = warp_n * 32 + jp * 16;
                int kr = kk + (lane & 7) + ((lane & 16) ? 8 : 0);
                int col = n0 + ((lane >> 3) & 1) * 8;
                uint32_t r0, r1, r2, r3;
                ldsm_x4_t(r0, r1, r2, r3, smem_u32(&Bs[st][kr][col]));
                bfr[jp*2][0] = r0; bfr[jp*2+1][0] = r1;
                bfr[jp*2][1] = r2; bfr[jp*2+1][1] = r3;
            }
            #pragma unroll
            for (int i = 0; i < 4; i++)
                #pragma unroll
                for (int j = 0; j < 4; j++)
                    mma16816(acc[i][j], af[i], bfr[j]);
        }
        __syncthreads();
    }

    size_t blockRow = (size_t)blockIdx.y * TM;
    size_t blockCol = (size_t)blockIdx.x * TN;
    #pragma unroll
    for (int i = 0; i < 4; i++) {
        size_t r0 = blockRow + warp_m * 64 + i * 16 + (lane >> 2);
        #pragma unroll
        for (int j = 0; j < 4; j++) {
            size_t c0 = blockCol + warp_n * 32 + j * 8 + (lane & 3) * 2;
            if constexpr (sizeof(OutT) == 4) {
                float2 v0 = make_float2(acc[i][j][0], acc[i][j][1]);
                float2 v1 = make_float2(acc[i][j][2], acc[i][j][3]);
                if (Res) {
                    const float2 q0 = *(const float2*)(Res + r0 * Nc + c0);
                    const float2 q1 = *(const float2*)(Res + (r0 + 8) * Nc + c0);
                    v0.x += q0.x; v0.y += q0.y; v1.x += q1.x; v1.y += q1.y;
                }
                *(float2*)((float*)C + r0 * Nc + c0) = v0;
                *(float2*)((float*)C + (r0 + 8) * Nc + c0) = v1;
            } else {
                uint32_t v0 = pack_bf16(acc[i][j][0], acc[i][j][1]);
                uint32_t v1 = pack_bf16(acc[i][j][2], acc[i][j][3]);
                *(uint32_t*)((bf16*)C + r0 * Nc + c0) = v0;
                *(uint32_t*)((bf16*)C + (r0 + 8) * Nc + c0) = v1;
            }
        }
    }
}

// ---------------- combine ---------------------------------------------------
__global__ void combine_kernel(const float* __restrict__ allh,
                               const float* __restrict__ w1, const float* __restrict__ w2,
                               float* __restrict__ h1, float* __restrict__ h2, int Rr) {
    int bs = blockIdx.x;
    int r = threadIdx.x;
    __shared__ float ws1[NN], ws2[NN];
    if (threadIdx.x < NN) {
        ws1[threadIdx.x] = w1[(size_t)bs * NN + threadIdx.x];
        if (w2) ws2[threadIdx.x] = w2[(size_t)bs * NN + threadIdx.x];
    }
    __syncthreads();
    const float* rowp = allh + (size_t)bs * NN * Rr;
    float a1 = 0.f, a2 = 0.f;
    #pragma unroll 8
    for (int n = 0; n < NN; n++) {
        float v = rowp[n * Rr + r];
        a1 += ws1[n] * v;
        if (w2) a2 += ws2[n] * v;
    }
    h1[(size_t)bs * Rr + r] = a1;
    if (w2) h2[(size_t)bs * Rr + r] = a2;
}

// ---------------- build T ---------------------------------------------------
__global__ void buildT_kernel(const float* __restrict__ h, const float* __restrict__ w,
                              bf16* __restrict__ T, int Rr) {
    int bs = blockIdx.x;
    __shared__ float hs[RKK];
    __shared__ float ws[NN];
    int tid = threadIdx.x;
    if (tid < Rr) hs[tid] = h[(size_t)bs * Rr + tid];
    if (tid < NN) ws[tid] = w[(size_t)bs * NN + tid];
    __syncthreads();
    int total = NN * Rr;
    bf16* Trow = T + (size_t)bs * total;
    for (int i = tid; i < total; i += 256) {
        int n = i / Rr;
        int r = i - n * Rr;
        Trow[i] = __float2bfloat16(ws[n] * hs[r]);
    }
}

// ================= bf16 tensor-core flash attention ==========================
// CTA: 64 queries (4 warps x 16 rows) x 64-key tiles, DH=64, causal.
#define KSTR 72
#define SC2 (0.125f * 1.44269504f)   // scale * log2(e)

__global__ __launch_bounds__(128)
void attn_mma_kernel(const bf16* __restrict__ Q, const bf16* __restrict__ K,
                     const bf16* __restrict__ V, bf16* __restrict__ O) {
    __shared__ bf16 Qs[64][KSTR];
    __shared__ bf16 Ks[2][64][KSTR];
    __shared__ bf16 Vs[2][64][KSTR];

    int qt = gridDim.x - 1 - blockIdx.x;    // long blocks first
    int h = blockIdx.y, b = blockIdx.z;
    int tid = threadIdx.x;
    int lane = tid & 31, w = tid >> 5;
    size_t headoff = (size_t)h * DHH;

    const bf16* Qbase = Q + ((size_t)(b * SS + qt * 64)) * DD + headoff;
    const bf16* Kbase = K + ((size_t)b * SS) * DD + headoff;
    const bf16* Vbase = V + ((size_t)b * SS) * DD + headoff;

    // Q tile (group 0)
    #pragma unroll
    for (int i = 0; i < 4; i++) {
        int c = tid + i * 128;
        int row = c >> 3, off = (c & 7) * 8;
        cp16(smem_u32(&Qs[row][off]), Qbase + (size_t)row * DD + off);
    }
    cp_commit();

    // KV tile 0 (group 1)
    {
        const bf16* kb = Kbase;
        const bf16* vb = Vbase;
        #pragma unroll
        for (int i = 0; i < 4; i++) {
            int c = tid + i * 128;
            int row = c >> 3, off = (c & 7) * 8;
            cp16(smem_u32(&Ks[0][row][off]), kb + (size_t)row * DD + off);
            cp16(smem_u32(&Vs[0][row][off]), vb + (size_t)row * DD + off);
        }
        cp_commit();
    }

    // wait for Q, load Q fragments
    cp_wait<1>();
    __syncthreads();
    uint32_t aq[4][4];
    #pragma unroll
    for (int kc = 0; kc < 4; kc++) {
        int row = w * 16 + (lane & 15);
        int col = kc * 16 + (lane >> 4) * 8;
        ldsm_x4(aq[kc][0], aq[kc][1], aq[kc][2], aq[kc][3], smem_u32(&Qs[row][col]));
    }

    float acc_o[8][4];
    #pragma unroll
    for (int nt = 0; nt < 8; nt++)
        #pragma unroll
        for (int v = 0; v < 4; v++) acc_o[nt][v] = 0.f;
    float m[2] = {-INFINITY, -INFINITY};
    float l[2] = {0.f, 0.f};

    int ntiles = qt + 1;
    for (int j = 0; j < ntiles; j++) {
        int st = j & 1;
        if (j + 1 < ntiles) {
            const bf16* kb = Kbase + (size_t)(j + 1) * 64 * DD;
            const bf16* vb = Vbase + (size_t)(j + 1) * 64 * DD;
            #pragma unroll
            for (int i = 0; i < 4; i++) {
                int c = tid + i * 128;
                int row = c >> 3, off = (c & 7) * 8;
                cp16(smem_u32(&Ks[st ^ 1][row][off]), kb + (size_t)row * DD + off);
                cp16(smem_u32(&Vs[st ^ 1][row][off]), vb + (size_t)row * DD + off);
            }
            cp_commit();
            cp_wait<1>();
        } else {
            cp_wait<0>();
        }
        __syncthreads();

        // ---- S = Q K^T ----
        float s[8][4];
        #pragma unroll
        for (int nt = 0; nt < 8; nt++)
            #pragma unroll
            for (int v = 0; v < 4; v++) s[nt][v] = 0.f;
        #pragma unroll
        for (int kc = 0; kc < 4; kc++) {
            uint32_t bk[8][2];
            #pragma unroll
            for (int np = 0; np < 4; np++) {
                int row = np * 16 + (lane & 7) + ((lane & 16) ? 8 : 0);
                int colk = kc * 16 + ((lane & 8) ? 8 : 0);
                uint32_t r0, r1, r2, r3;
                ldsm_x4(r0, r1, r2, r3, smem_u32(&Ks[st][row][colk]));
                bk[np*2][0] = r0; bk[np*2][1] = r1;
                bk[np*2+1][0] = r2; bk[np*2+1][1] = r3;
            }
            #pragma unroll
            for (int nt = 0; nt < 8; nt++)
                mma16816(s[nt], aq[kc], bk[nt]);
        }

        // ---- causal mask on diagonal tile ----
        if (j == qt) {
            int r0 = w * 16 + (lane >> 2);
            int cb = (lane & 3) * 2;
            #pragma unroll
            for (int nt = 0; nt < 8; nt++) {
                #pragma unroll
                for (int v = 0; v < 4; v++) {
                    int col = nt * 8 + cb + (v & 1);
                    int row = r0 + ((v & 2) ? 8 : 0);
                    if (col > row) s[nt][v] = -INFINITY;
                }
            }
        }

        // ---- online softmax (two row-halves per thread) ----
        #pragma unroll
        for (int rh = 0; rh < 2; rh++) {
            float mt = -INFINITY;
            #pragma unroll
            for (int nt = 0; nt < 8; nt++)
                mt = fmaxf(mt, fmaxf(s[nt][rh*2], s[nt][rh*2+1]));
            mt = fmaxf(mt, __shfl_xor_sync(0xffffffffu, mt, 1));
            mt = fmaxf(mt, __shfl_xor_sync(0xffffffffu, mt, 2));
            float mn = fmaxf(m[rh], mt);
            float corr = exp2f((m[rh] - mn) * SC2);
            m[rh] = mn;
            float ls = 0.f;
            #pragma unroll
            for (int nt = 0; nt < 8; nt++) {
                float p0 = exp2f((s[nt][rh*2]   - mn) * SC2);
                float p1 = exp2f((s[nt][rh*2+1] - mn) * SC2);
                s[nt][rh*2] = p0; s[nt][rh*2+1] = p1;
                ls += p0 + p1;
            }
            ls += __shfl_xor_sync(0xffffffffu, ls, 1);
            ls += __shfl_xor_sync(0xffffffffu, ls, 2);
            l[rh] = l[rh] * corr + ls;
            #pragma unroll
            for (int nt = 0; nt < 8; nt++) {
                acc_o[nt][rh*2]   *= corr;
                acc_o[nt][rh*2+1] *= corr;
            }
        }

        // ---- O += P V ----
        #pragma unroll
        for (int kc = 0; kc < 4; kc++) {
            uint32_t pa[4];
            pa[0] = pack_bf16(s[2*kc][0],   s[2*kc][1]);
            pa[1] = pack_bf16(s[2*kc][2],   s[2*kc][3]);
            pa[2] = pack_bf16(s[2*kc+1][0], s[2*kc+1][1]);
            pa[3] = pack_bf16(s[2*kc+1][2], s[2*kc+1][3]);
            uint32_t bv[8][2];
            #pragma unroll
            for (int np = 0; np < 4; np++) {
                int kr = kc * 16 + (lane & 7) + ((lane & 16) ? 8 : 0);
                int col = np * 16 + ((lane & 8) ? 8 : 0);
                uint32_t r0, r1, r2, r3;
                ldsm_x4_t(r0, r1, r2, r3, smem_u32(&Vs[st][kr][col]));
                bv[np*2][0] = r0; bv[np*2+1][0] = r1;
                bv[np*2][1] = r2; bv[np*2+1][1] = r3;
            }
            #pragma unroll
            for (int nt = 0; nt < 8; nt++)
                mma16816(acc_o[nt], pa, bv[nt]);
        }
        __syncthreads();
    }

    // ---- epilogue ----
    float inv0 = 1.f / l[0];
    float inv1 = 1.f / l[1];
    int row0 = qt * 64 + w * 16 + (lane >> 2);
    bf16* Ob = O + ((size_t)b * SS) * DD + headoff;
    #pragma unroll
    for (int nt = 0; nt < 8; nt++) {
        int col = nt * 8 + (lane & 3) * 2;
        *(uint32_t*)(Ob + (size_t)row0 * DD + col)       = pack_bf16(acc_o[nt][0] * inv0, acc_o[nt][1] * inv0);
        *(uint32_t*)(Ob + (size_t)(row0 + 8) * DD + col) = pack_bf16(acc_o[nt][2] * inv1, acc_o[nt][3] * inv1);
    }
}

// ---------------- launch -----------------------------------------------------
extern "C" void kernel_launch(void* const* d_in, const int* in_sizes, int n_in,
                              void* d_out, int out_size) {
    const float* x       = (const float*)d_in[0];
    const float* f_qk    = (const float*)d_in[1];
    const float* f_v     = (const float*)d_in[2];
    const float* r_qk    = (const float*)d_in[3];
    const float* r_v     = (const float*)d_in[4];
    const float* f_know  = (const float*)d_in[5];
    const float* r_know  = (const float*)d_in[6];
    const float* W_O     = (const float*)d_in[7];
    const float* gamma1  = (const float*)d_in[8];
    const float* beta1   = (const float*)d_in[9];
    const float* gamma2  = (const float*)d_in[10];
    const float* beta2   = (const float*)d_in[11];
    const float* w_fq    = (const float*)d_in[12];
    const float* w_fk    = (const float*)d_in[13];
    const float* w_fv    = (const float*)d_in[14];
    const float* w_rq    = (const float*)d_in[15];
    const float* w_rk    = (const float*)d_in[16];
    const float* w_rv    = (const float*)d_in[17];
    const float* w_know_f= (const float*)d_in[18];
    const float* w_know_r= (const float*)d_in[19];
    float* out = (float*)d_out;

    bf16 *Bqk, *Bv, *Bkn, *WOT, *nx, *rqk, *rv, *rkn, *Tq, *Tk, *Tv, *Tkn, *attn;
    bf16 *Qb, *Kb, *Vb;
    float *allh_qk, *allh_v, *allh_kn, *hq, *hk, *hv, *hkn, *x1;
    cudaGetSymbolAddress((void**)&Bqk, g_Bqk);
    cudaGetSymbolAddress((void**)&Bv,  g_Bv);
    cudaGetSymbolAddress((void**)&Bkn, g_Bkn);
    cudaGetSymbolAddress((void**)&WOT, g_WOT);
    cudaGetSymbolAddress((void**)&rqk, g_rqk);
    cudaGetSymbolAddress((void**)&rv,  g_rv);
    cudaGetSymbolAddress((void**)&rkn, g_rkn);
    cudaGetSymbolAddress((void**)&nx,  g_nx);
    cudaGetSymbolAddress((void**)&allh_qk, g_allh_qk);
    cudaGetSymbolAddress((void**)&allh_v,  g_allh_v);
    cudaGetSymbolAddress((void**)&allh_kn, g_allh_kn);
    cudaGetSymbolAddress((void**)&hq, g_hq);
    cudaGetSymbolAddress((void**)&hk, g_hk);
    cudaGetSymbolAddress((void**)&hv, g_hv);
    cudaGetSymbolAddress((void**)&hkn, g_hkn);
    cudaGetSymbolAddress((void**)&Tq, g_Tq);
    cudaGetSymbolAddress((void**)&Tk, g_Tk);
    cudaGetSymbolAddress((void**)&Tv, g_Tv);
    cudaGetSymbolAddress((void**)&Tkn, g_Tkn);
    cudaGetSymbolAddress((void**)&Qb, g_Qb);
    cudaGetSymbolAddress((void**)&Kb, g_Kb);
    cudaGetSymbolAddress((void**)&Vb, g_Vb);
    cudaGetSymbolAddress((void**)&attn, g_attn);
    cudaGetSymbolAddress((void**)&x1, g_x1);

    // pack neuron matrices + conversions
    pack_f_kernel<<<(DD*NN*RR + 255)/256, 256>>>(f_qk, Bqk, RR);
    pack_f_kernel<<<(DD*NN*RR + 255)/256, 256>>>(f_v,  Bv,  RR);
    pack_f_kernel<<<(DD*NN*RKK + 255)/256, 256>>>(f_know, Bkn, RKK);
    transpose_kernel<<<dim3(32,32), dim3(32,8)>>>(W_O, WOT);
    cvt_bf16_kernel<<<(NR*DD + 255)/256, 256>>>(r_qk, rqk, NR*DD);
    cvt_bf16_kernel<<<(NR*DD + 255)/256, 256>>>(r_v,  rv,  NR*DD);
    cvt_bf16_kernel<<<(NRK*DD + 255)/256, 256>>>(r_know, rkn, NRK*DD);

    // --- attention circuit ---
    ln_kernel<<<BSZ, 256>>>(x, gamma1, beta1, nx);

    hgemm_kernel<float><<<dim3(NR/TN, BSZ/TM), 256>>>(nx, Bqk, allh_qk, nullptr, BSZ, NR, DD);
    hgemm_kernel<float><<<dim3(NR/TN, BSZ/TM), 256>>>(nx, Bv,  allh_v,  nullptr, BSZ, NR, DD);

    combine_kernel<<<BSZ, RR>>>(allh_qk, w_fq, w_fk, hq, hk, RR);
    combine_kernel<<<BSZ, RR>>>(allh_v,  w_fv, nullptr, hv, nullptr, RR);

    buildT_kernel<<<BSZ, 256>>>(hq, w_rq, Tq, RR);
    buildT_kernel<<<BSZ, 256>>>(hk, w_rk, Tk, RR);
    buildT_kernel<<<BSZ, 256>>>(hv, w_rv, Tv, RR);

    hgemm_kernel<bf16><<<dim3(DD/TN, BSZ/TM), 256>>>(Tq, rqk, Qb, nullptr, BSZ, DD, NR);
    hgemm_kernel<bf16><<<dim3(DD/TN, BSZ/TM), 256>>>(Tk, rqk, Kb, nullptr, BSZ, DD, NR);
    hgemm_kernel<bf16><<<dim3(DD/TN, BSZ/TM), 256>>>(Tv, rv,  Vb, nullptr, BSZ, DD, NR);

    attn_mma_kernel<<<dim3(SS/64, HH, BB), 128>>>(Qb, Kb, Vb, attn);

    // x1 = x + attn @ W_O^T
    hgemm_kernel<float><<<dim3(DD/TN, BSZ/TM), 256>>>(attn, WOT, x1, x, BSZ, DD, DD);

    // --- knowledge circuit ---
    ln_kernel<<<BSZ, 256>>>(x1, gamma2, beta2, nx);
    hgemm_kernel<float><<<dim3(NRK/TN, BSZ/TM), 256>>>(nx, Bkn, allh_kn, nullptr, BSZ, NRK, DD);
    combine_kernel<<<BSZ, RKK>>>(allh_kn, w_know_f, nullptr, hkn, nullptr, RKK);
    buildT_kernel<<<BSZ, 256>>>(hkn, w_know_r, Tkn, RKK);
    // out = x1 + Tkn @ r_know
    hgemm_kernel<float><<<dim3(DD/TN, BSZ/TM), 256>>>(Tkn, rkn, out, x1, BSZ, DD, NRK);
}

// round 7
// speedup vs baseline: 6.2772x; 1.0035x over previous
#include <cuda_runtime.h>
#include <cuda_bf16.h>
#include <math.h>
#include <stdint.h>

// Problem constants
#define BB 2
#define SS 2048
#define DD 1024
#define HH 16
#define RR 64
#define NN 32
#define RKK 128
#define DHH 64
#define BSZ (BB*SS)          // 4096 tokens
#define NR (NN*RR)           // 2048
#define NRK (NN*RKK)         // 4096
#define LN_EPS 1e-5f

typedef __nv_bfloat16 bf16;

// ---------------- scratch ----------------------------------------------------
__device__ bf16  g_Bqkv[(size_t)DD*2*NR];     // [D, 4096] = [f_qk | f_v] packed
__device__ bf16  g_Bkn[(size_t)DD*NRK];       // [D, 4096]
__device__ bf16  g_WOT[DD*DD];
__device__ bf16  g_rqk[(size_t)NR*DD];
__device__ bf16  g_rv [(size_t)NR*DD];
__device__ bf16  g_rkn[(size_t)NRK*DD];
__device__ bf16  g_nx [BSZ*DD];
__device__ float g_allh[(size_t)BSZ*4096];    // reused: feature qkv AND knowledge
__device__ bf16  g_Tqk[(size_t)2*BSZ*NR];     // [Tq ; Tk]
__device__ bf16  g_Tv [(size_t)BSZ*NR];
__device__ bf16  g_Tkn[(size_t)BSZ*NRK];
__device__ bf16  g_QKb[(size_t)2*BSZ*DD];     // [Q ; K] bf16
__device__ bf16  g_Vb[BSZ*DD];
__device__ bf16  g_attn[BSZ*DD];
__device__ float g_x1[BSZ*DD];

// ---------------- helpers ----------------------------------------------------
__device__ __forceinline__ uint32_t smem_u32(const void* p) {
    return (uint32_t)__cvta_generic_to_shared(p);
}
__device__ __forceinline__ void cp16(uint32_t saddr, const void* gaddr) {
    asm volatile("cp.async.cg.shared.global [%0], [%1], 16;\n" :: "r"(saddr), "l"(gaddr));
}
__device__ __forceinline__ void cp_commit() { asm volatile("cp.async.commit_group;\n"); }
template<int N> __device__ __forceinline__ void cp_wait() {
    asm volatile("cp.async.wait_group %0;\n" :: "n"(N));
}
__device__ __forceinline__ void ldsm_x4(uint32_t& r0, uint32_t& r1, uint32_t& r2, uint32_t& r3, uint32_t addr) {
    asm volatile("ldmatrix.sync.aligned.m8n8.x4.shared.b16 {%0,%1,%2,%3}, [%4];\n"
                 : "=r"(r0), "=r"(r1), "=r"(r2), "=r"(r3) : "r"(addr));
}
__device__ __forceinline__ void ldsm_x4_t(uint32_t& r0, uint32_t& r1, uint32_t& r2, uint32_t& r3, uint32_t addr) {
    asm volatile("ldmatrix.sync.aligned.m8n8.x4.trans.shared.b16 {%0,%1,%2,%3}, [%4];\n"
                 : "=r"(r0), "=r"(r1), "=r"(r2), "=r"(r3) : "r"(addr));
}
__device__ __forceinline__ void mma16816(float* d, const uint32_t* a, const uint32_t* b) {
    asm volatile("mma.sync.aligned.m16n8k16.row.col.f32.bf16.bf16.f32 "
                 "{%0,%1,%2,%3}, {%4,%5,%6,%7}, {%8,%9}, {%0,%1,%2,%3};\n"
                 : "+f"(d[0]), "+f"(d[1]), "+f"(d[2]), "+f"(d[3])
                 : "r"(a[0]), "r"(a[1]), "r"(a[2]), "r"(a[3]), "r"(b[0]), "r"(b[1]));
}
__device__ __forceinline__ uint32_t pack_bf16(float x, float y) {
    __nv_bfloat162 t = __floats2bfloat162_rn(x, y);
    return *(uint32_t*)&t;
}

// ---------------- pack f[n,d,r] -> out[d*stride + colOff + n*Rr + r] ---------
__global__ void pack_f_kernel(const float* __restrict__ in, bf16* __restrict__ out,
                              int Rr, int stride, int colOff) {
    int total = DD * NN * Rr;
    int idx = blockIdx.x * blockDim.x + threadIdx.x;
    if (idx >= total) return;
    int nr = NN * Rr;
    int d = idx / nr;
    int rem = idx - d * nr;
    int n = rem / Rr;
    int r = rem - n * Rr;
    out[(size_t)d * stride + colOff + rem] = __float2bfloat16(in[((size_t)n * DD + d) * Rr + r]);
}

__global__ void cvt_bf16_kernel(const float* __restrict__ in, bf16* __restrict__ out, int n) {
    int i = blockIdx.x * blockDim.x + threadIdx.x;
    if (i < n) out[i] = __float2bfloat16(in[i]);
}

__global__ void transpose_kernel(const float* __restrict__ in, bf16* __restrict__ out) {
    __shared__ float tile[32][33];
    int x = blockIdx.x * 32 + threadIdx.x;
    int y = blockIdx.y * 32 + threadIdx.y;
    #pragma unroll
    for (int i = 0; i < 32; i += 8)
        tile[threadIdx.y + i][threadIdx.x] = in[(size_t)(y + i) * DD + x];
    __syncthreads();
    x = blockIdx.y * 32 + threadIdx.x;
    y = blockIdx.x * 32 + threadIdx.y;
    #pragma unroll
    for (int i = 0; i < 32; i += 8)
        out[(size_t)(y + i) * DD + x] = __float2bfloat16(tile[threadIdx.x][threadIdx.y + i]);
}

// ---------------- LayerNorm --------------------------------------------------
__global__ void ln_kernel(const float* __restrict__ x, const float* __restrict__ g,
                          const float* __restrict__ b, bf16* __restrict__ out) {
    int row = blockIdx.x;
    const float* xr = x + (size_t)row * DD;
    int c = threadIdx.x * 4;
    float4 xv = *(const float4*)(xr + c);
    float s  = xv.x + xv.y + xv.z + xv.w;
    float sq = xv.x*xv.x + xv.y*xv.y + xv.z*xv.z + xv.w*xv.w;
    #pragma unroll
    for (int o = 16; o > 0; o >>= 1) {
        s  += __shfl_xor_sync(0xffffffffu, s,  o);
        sq += __shfl_xor_sync(0xffffffffu, sq, o);
    }
    __shared__ float ss[8], ssq[8];
    __shared__ float mean_s, rstd_s;
    int wid = threadIdx.x >> 5, lid = threadIdx.x & 31;
    if (lid == 0) { ss[wid] = s; ssq[wid] = sq; }
    __syncthreads();
    if (threadIdx.x == 0) {
        float S = 0.f, SQ = 0.f;
        #pragma unroll
        for (int i = 0; i < 8; i++) { S += ss[i]; SQ += ssq[i]; }
        float mu  = S * (1.f / DD);
        float var = SQ * (1.f / DD) - mu * mu;
        mean_s = mu;
        rstd_s = rsqrtf(var + LN_EPS);
    }
    __syncthreads();
    float mu = mean_s, rs = rstd_s;
    float4 gv = *(const float4*)(g + c);
    float4 bv = *(const float4*)(b + c);
    bf16* orow = out + (size_t)row * DD + c;
    orow[0] = __float2bfloat16(gv.x * (xv.x - mu) * rs + bv.x);
    orow[1] = __float2bfloat16(gv.y * (xv.y - mu) * rs + bv.y);
    orow[2] = __float2bfloat16(gv.z * (xv.z - mu) * rs + bv.z);
    orow[3] = __float2bfloat16(gv.w * (xv.w - mu) * rs + bv.w);
}

// ================== bf16 tensor-core GEMM, 3-stage cp.async pipeline =========
#define TM 128
#define TN 128
#define TK 32
#define ASTR 40
#define BSTR 136
#define ASZ (TM*ASTR)            // elems per A stage
#define BSZE (TK*BSTR)           // elems per B stage
#define HSMEM (3*(ASZ+BSZE)*2)   // bytes

template<typename OutT>
__global__ __launch_bounds__(256, 2)
void hgemm_kernel(const bf16* __restrict__ A, const bf16* __restrict__ B,
                  OutT* __restrict__ C, const float* __restrict__ Res,
                  int M, int Nc, int K) {
    extern __shared__ char dynsm[];
    bf16* As = (bf16*)dynsm;                 // [3][TM][ASTR]
    bf16* Bs = (bf16*)dynsm + 3 * ASZ;       // [3][TK][BSTR]
    int tid = threadIdx.x;
    int lane = tid & 31;
    int warp = tid >> 5;
    int warp_m = warp & 1;
    int warp_n = warp >> 1;

    const bf16* Ab = A + (size_t)blockIdx.y * TM * K;
    const bf16* Bb = B + (size_t)blockIdx.x * TN;

    float acc[4][4][4];
    #pragma unroll
    for (int i = 0; i < 4; i++)
        #pragma unroll
        for (int j = 0; j < 4; j++)
            #pragma unroll
            for (int v = 0; v < 4; v++) acc[i][j][v] = 0.f;

    int a_row = tid >> 1;
    int a_c0  = (tid & 1) * 16;
    int b_row = tid >> 4;
    int b_c0  = (tid & 15) * 8;

    int KT = K / TK;
    // prologue: stages 0,1
    #pragma unroll
    for (int p = 0; p < 2; p++) {
        int k0 = p * TK;
        bf16* Ast = As + p * ASZ;
        bf16* Bst = Bs + p * BSZE;
        uint32_t sa = smem_u32(Ast + a_row * ASTR + a_c0);
        cp16(sa,      Ab + (size_t)a_row * K + k0 + a_c0);
        cp16(sa + 16, Ab + (size_t)a_row * K + k0 + a_c0 + 8);
        uint32_t sb0 = smem_u32(Bst + b_row * BSTR + b_c0);
        uint32_t sb1 = smem_u32(Bst + (b_row + 16) * BSTR + b_c0);
        cp16(sb0, Bb + (size_t)(k0 + b_row) * Nc + b_c0);
        cp16(sb1, Bb + (size_t)(k0 + b_row + 16) * Nc + b_c0);
        cp_commit();
    }

    int st = 0;
    for (int kt = 0; kt < KT; kt++) {
        if (kt + 1 < KT) cp_wait<1>(); else cp_wait<0>();
        __syncthreads();
        if (kt + 2 < KT) {
            int ldst = st + 2; if (ldst >= 3) ldst -= 3;
            int k0 = (kt + 2) * TK;
            bf16* Ast = As + ldst * ASZ;
            bf16* Bst = Bs + ldst * BSZE;
            uint32_t sa = smem_u32(Ast + a_row * ASTR + a_c0);
            cp16(sa,      Ab + (size_t)a_row * K + k0 + a_c0);
            cp16(sa + 16, Ab + (size_t)a_row * K + k0 + a_c0 + 8);
            uint32_t sb0 = smem_u32(Bst + b_row * BSTR + b_c0);
            uint32_t sb1 = smem_u32(Bst + (b_row + 16) * BSTR + b_c0);
            cp16(sb0, Bb + (size_t)(k0 + b_row) * Nc + b_c0);
            cp16(sb1, Bb + (size_t)(k0 + b_row + 16) * Nc + b_c0);
            cp_commit();
        }
        bf16* Ast = As + st * ASZ;
        bf16* Bst = Bs + st * BSZE;
        #pragma unroll
        for (int kk = 0; kk < TK; kk += 16) {
            uint32_t af[4][4];
            #pragma unroll
            for (int i = 0; i < 4; i++) {
                int row = warp_m * 64 + i * 16 + (lane & 15);
                int col = kk + (lane >> 4) * 8;
                ldsm_x4(af[i][0], af[i][1], af[i][2], af[i][3], smem_u32(Ast + row * ASTR + col));
            }
            uint32_t bfr[4][2];
            #pragma unroll
            for (int jp = 0; jp < 2; jp++) {
                int n0 = warp_n * 32 + jp * 16;
                int kr = kk + (lane & 7) + ((lane & 16) ? 8 : 0);
                int col = n0 + ((lane >> 3) & 1) * 8;
                uint32_t r0, r1, r2, r3;
                ldsm_x4_t(r0, r1, r2, r3, smem_u32(Bst + kr * BSTR + col));
                bfr[jp*2][0] = r0; bfr[jp*2+1][0] = r1;
                bfr[jp*2][1] = r2; bfr[jp*2+1][1] = r3;
            }
            #pragma unroll
            for (int i = 0; i < 4; i++)
                #pragma unroll
                for (int j = 0; j < 4; j++)
                    mma16816(acc[i][j], af[i], bfr[j]);
        }
        st++; if (st >= 3) st -= 3;
        __syncthreads();
    }

    size_t blockRow = (size_t)blockIdx.y * TM;
    size_t blockCol = (size_t)blockIdx.x * TN;
    #pragma unroll
    for (int i = 0; i < 4; i++) {
        size_t r0 = blockRow + warp_m * 64 + i * 16 + (lane >> 2);
        #pragma unroll
        for (int j = 0; j < 4; j++) {
            size_t c0 = blockCol + warp_n * 32 + j * 8 + (lane & 3) * 2;
            if constexpr (sizeof(OutT) == 4) {
                float2 v0 = make_float2(acc[i][j][0], acc[i][j][1]);
                float2 v1 = make_float2(acc[i][j][2], acc[i][j][3]);
                if (Res) {
                    const float2 q0 = *(const float2*)(Res + r0 * Nc + c0);
                    const float2 q1 = *(const float2*)(Res + (r0 + 8) * Nc + c0);
                    v0.x += q0.x; v0.y += q0.y; v1.x += q1.x; v1.y += q1.y;
                }
                *(float2*)((float*)C + r0 * Nc + c0) = v0;
                *(float2*)((float*)C + (r0 + 8) * Nc + c0) = v1;
            } else {
                *(uint32_t*)((bf16*)C + r0 * Nc + c0)       = pack_bf16(acc[i][j][0], acc[i][j][1]);
                *(uint32_t*)((bf16*)C + (r0 + 8) * Nc + c0) = pack_bf16(acc[i][j][2], acc[i][j][3]);
            }
        }
    }
}

// ---------------- fused combine + buildT ------------------------------------
// h[r] = sum_n wf[n]*allh[bs, n*Rr+r];  T[bs, n*Rr+r] = wr[n]*h[r]
__global__ void combineT_kernel(const float* __restrict__ allh, int stride,
                                const float* __restrict__ wf1, const float* __restrict__ wf2,
                                const float* __restrict__ wr1, const float* __restrict__ wr2,
                                bf16* __restrict__ T1, bf16* __restrict__ T2, int Rr) {
    int bs = blockIdx.x;
    int tid = threadIdx.x;           // 256
    __shared__ float h1s[RKK], h2s[RKK];
    __shared__ float wf1s[NN], wf2s[NN], wr1s[NN], wr2s[NN];
    if (tid < NN) {
        wf1s[tid] = wf1[(size_t)bs * NN + tid];
        wr1s[tid] = wr1[(size_t)bs * NN + tid];
        if (wf2) { wf2s[tid] = wf2[(size_t)bs * NN + tid]; wr2s[tid] = wr2[(size_t)bs * NN + tid]; }
    }
    __syncthreads();
    if (tid < Rr) {
        const float* rowp = allh + (size_t)bs * stride;
        float a1 = 0.f, a2 = 0.f;
        #pragma unroll 8
        for (int n = 0; n < NN; n++) {
            float v = rowp[n * Rr + tid];
            a1 += wf1s[n] * v;
            if (wf2) a2 += wf2s[n] * v;
        }
        h1s[tid] = a1;
        if (wf2) h2s[tid] = a2;
    }
    __syncthreads();
    int total = NN * Rr;
    bf16* T1row = T1 + (size_t)bs * total;
    bf16* T2row = wf2 ? (T2 + (size_t)bs * total) : nullptr;
    for (int i = tid; i < total; i += 256) {
        int n = i / Rr;
        int r = i - n * Rr;
        T1row[i] = __float2bfloat16(wr1s[n] * h1s[r]);
        if (wf2) T2row[i] = __float2bfloat16(wr2s[n] * h2s[r]);
    }
}

// ================= bf16 tensor-core flash attention ==========================
#define KSTR 72
#define SC2 (0.125f * 1.44269504f)

__global__ __launch_bounds__(128)
void attn_mma_kernel(const bf16* __restrict__ Q, const bf16* __restrict__ K,
                     const bf16* __restrict__ V, bf16* __restrict__ O) {
    __shared__ bf16 Qs[64][KSTR];
    __shared__ bf16 Ks[2][64][KSTR];
    __shared__ bf16 Vs[2][64][KSTR];

    int qt = gridDim.x - 1 - blockIdx.x;
    int h = blockIdx.y, b = blockIdx.z;
    int tid = threadIdx.x;
    int lane = tid & 31, w = tid >> 5;
    size_t headoff = (size_t)h * DHH;

    const bf16* Qbase = Q + ((size_t)(b * SS + qt * 64)) * DD + headoff;
    const bf16* Kbase = K + ((size_t)b * SS) * DD + headoff;
    const bf16* Vbase = V + ((size_t)b * SS) * DD + headoff;

    #pragma unroll
    for (int i = 0; i < 4; i++) {
        int c = tid + i * 128;
        int row = c >> 3, off = (c & 7) * 8;
        cp16(smem_u32(&Qs[row][off]), Qbase + (size_t)row * DD + off);
    }
    cp_commit();
    {
        #pragma unroll
        for (int i = 0; i < 4; i++) {
            int c = tid + i * 128;
            int row = c >> 3, off = (c & 7) * 8;
            cp16(smem_u32(&Ks[0][row][off]), Kbase + (size_t)row * DD + off);
            cp16(smem_u32(&Vs[0][row][off]), Vbase + (size_t)row * DD + off);
        }
        cp_commit();
    }

    cp_wait<1>();
    __syncthreads();
    uint32_t aq[4][4];
    #pragma unroll
    for (int kc = 0; kc < 4; kc++) {
        int row = w * 16 + (lane & 15);
        int col = kc * 16 + (lane >> 4) * 8;
        ldsm_x4(aq[kc][0], aq[kc][1], aq[kc][2], aq[kc][3], smem_u32(&Qs[row][col]));
    }

    float acc_o[8][4];
    #pragma unroll
    for (int nt = 0; nt < 8; nt++)
        #pragma unroll
        for (int v = 0; v < 4; v++) acc_o[nt][v] = 0.f;
    float m[2] = {-INFINITY, -INFINITY};
    float l[2] = {0.f, 0.f};

    int ntiles = qt + 1;
    for (int j = 0; j < ntiles; j++) {
        int st = j & 1;
        if (j + 1 < ntiles) {
            const bf16* kb = Kbase + (size_t)(j + 1) * 64 * DD;
            const bf16* vb = Vbase + (size_t)(j + 1) * 64 * DD;
            #pragma unroll
            for (int i = 0; i < 4; i++) {
                int c = tid + i * 128;
                int row = c >> 3, off = (c & 7) * 8;
                cp16(smem_u32(&Ks[st ^ 1][row][off]), kb + (size_t)row * DD + off);
                cp16(smem_u32(&Vs[st ^ 1][row][off]), vb + (size_t)row * DD + off);
            }
            cp_commit();
            cp_wait<1>();
        } else {
            cp_wait<0>();
        }
        __syncthreads();

        float s[8][4];
        #pragma unroll
        for (int nt = 0; nt < 8; nt++)
            #pragma unroll
            for (int v = 0; v < 4; v++) s[nt][v] = 0.f;
        #pragma unroll
        for (int kc = 0; kc < 4; kc++) {
            uint32_t bk[8][2];
            #pragma unroll
            for (int np = 0; np < 4; np++) {
                int row = np * 16 + (lane & 7) + ((lane & 16) ? 8 : 0);
                int colk = kc * 16 + ((lane & 8) ? 8 : 0);
                uint32_t r0, r1, r2, r3;
                ldsm_x4(r0, r1, r2, r3, smem_u32(&Ks[st][row][colk]));
                bk[np*2][0] = r0; bk[np*2][1] = r1;
                bk[np*2+1][0] = r2; bk[np*2+1][1] = r3;
            }
            #pragma unroll
            for (int nt = 0; nt < 8; nt++)
                mma16816(s[nt], aq[kc], bk[nt]);
        }

        if (j == qt) {
            int r0 = w * 16 + (lane >> 2);
            int cb = (lane & 3) * 2;
            #pragma unroll
            for (int nt = 0; nt < 8; nt++) {
                #pragma unroll
                for (int v = 0; v < 4; v++) {
                    int col = nt * 8 + cb + (v & 1);
                    int row = r0 + ((v & 2) ? 8 : 0);
                    if (col > row) s[nt][v] = -INFINITY;
                }
            }
        }

        #pragma unroll
        for (int rh = 0; rh < 2; rh++) {
            float mt = -INFINITY;
            #pragma unroll
            for (int nt = 0; nt < 8; nt++)
                mt = fmaxf(mt, fmaxf(s[nt][rh*2], s[nt][rh*2+1]));
            mt = fmaxf(mt, __shfl_xor_sync(0xffffffffu, mt, 1));
            mt = fmaxf(mt, __shfl_xor_sync(0xffffffffu, mt, 2));
            float mn = fmaxf(m[rh], mt);
            float corr = exp2f((m[rh] - mn) * SC2);
            m[rh] = mn;
            float ls = 0.f;
            #pragma unroll
            for (int nt = 0; nt < 8; nt++) {
                float p0 = exp2f((s[nt][rh*2]   - mn) * SC2);
                float p1 = exp2f((s[nt][rh*2+1] - mn) * SC2);
                s[nt][rh*2] = p0; s[nt][rh*2+1] = p1;
                ls += p0 + p1;
            }
            ls += __shfl_xor_sync(0xffffffffu, ls, 1);
            ls += __shfl_xor_sync(0xffffffffu, ls, 2);
            l[rh] = l[rh] * corr + ls;
            #pragma unroll
            for (int nt = 0; nt < 8; nt++) {
                acc_o[nt][rh*2]   *= corr;
                acc_o[nt][rh*2+1] *= corr;
            }
        }

        #pragma unroll
        for (int kc = 0; kc < 4; kc++) {
            uint32_t pa[4];
            pa[0] = pack_bf16(s[2*kc][0],   s[2*kc][1]);
            pa[1] = pack_bf16(s[2*kc][2],   s[2*kc][3]);
            pa[2] = pack_bf16(s[2*kc+1][0], s[2*kc+1][1]);
            pa[3] = pack_bf16(s[2*kc+1][2], s[2*kc+1][3]);
            uint32_t bv[8][2];
            #pragma unroll
            for (int np = 0; np < 4; np++) {
                int kr = kc * 16 + (lane & 7) + ((lane & 16) ? 8 : 0);
                int col = np * 16 + ((lane & 8) ? 8 : 0);
                uint32_t r0, r1, r2, r3;
                ldsm_x4_t(r0, r1, r2, r3, smem_u32(&Vs[st][kr][col]));
                bv[np*2][0] = r0; bv[np*2+1][0] = r1;
                bv[np*2][1] = r2; bv[np*2+1][1] = r3;
            }
            #pragma unroll
            for (int nt = 0; nt < 8; nt++)
                mma16816(acc_o[nt], pa, bv[nt]);
        }
        __syncthreads();
    }

    float inv0 = 1.f / l[0];
    float inv1 = 1.f / l[1];
    int row0 = qt * 64 + w * 16 + (lane >> 2);
    bf16* Ob = O + ((size_t)b * SS) * DD + headoff;
    #pragma unroll
    for (int nt = 0; nt < 8; nt++) {
        int col = nt * 8 + (lane & 3) * 2;
        *(uint32_t*)(Ob + (size_t)row0 * DD + col)       = pack_bf16(acc_o[nt][0] * inv0, acc_o[nt][1] * inv0);
        *(uint32_t*)(Ob + (size_t)(row0 + 8) * DD + col) = pack_bf16(acc_o[nt][2] * inv1, acc_o[nt][3] * inv1);
    }
}

// ---------------- launch -----------------------------------------------------
extern "C" void kernel_launch(void* const* d_in, const int* in_sizes, int n_in,
                              void* d_out, int out_size) {
    const float* x       = (const float*)d_in[0];
    const float* f_qk    = (const float*)d_in[1];
    const float* f_v     = (const float*)d_in[2];
    const float* r_qk    = (const float*)d_in[3];
    const float* r_v     = (const float*)d_in[4];
    const float* f_know  = (const float*)d_in[5];
    const float* r_know  = (const float*)d_in[6];
    const float* W_O     = (const float*)d_in[7];
    const float* gamma1  = (const float*)d_in[8];
    const float* beta1   = (const float*)d_in[9];
    const float* gamma2  = (const float*)d_in[10];
    const float* beta2   = (const float*)d_in[11];
    const float* w_fq    = (const float*)d_in[12];
    const float* w_fk    = (const float*)d_in[13];
    const float* w_fv    = (const float*)d_in[14];
    const float* w_rq    = (const float*)d_in[15];
    const float* w_rk    = (const float*)d_in[16];
    const float* w_rv    = (const float*)d_in[17];
    const float* w_know_f= (const float*)d_in[18];
    const float* w_know_r= (const float*)d_in[19];
    float* out = (float*)d_out;

    bf16 *Bqkv, *Bkn, *WOT, *nx, *rqk, *rv, *rkn, *Tqk, *Tv, *Tkn, *QKb, *Vb, *attn;
    float *allh, *x1;
    cudaGetSymbolAddress((void**)&Bqkv, g_Bqkv);
    cudaGetSymbolAddress((void**)&Bkn, g_Bkn);
    cudaGetSymbolAddress((void**)&WOT, g_WOT);
    cudaGetSymbolAddress((void**)&rqk, g_rqk);
    cudaGetSymbolAddress((void**)&rv,  g_rv);
    cudaGetSymbolAddress((void**)&rkn, g_rkn);
    cudaGetSymbolAddress((void**)&nx,  g_nx);
    cudaGetSymbolAddress((void**)&allh, g_allh);
    cudaGetSymbolAddress((void**)&Tqk, g_Tqk);
    cudaGetSymbolAddress((void**)&Tv,  g_Tv);
    cudaGetSymbolAddress((void**)&Tkn, g_Tkn);
    cudaGetSymbolAddress((void**)&QKb, g_QKb);
    cudaGetSymbolAddress((void**)&Vb,  g_Vb);
    cudaGetSymbolAddress((void**)&attn, g_attn);
    cudaGetSymbolAddress((void**)&x1, g_x1);

    cudaFuncSetAttribute(hgemm_kernel<float>, cudaFuncAttributeMaxDynamicSharedMemorySize, HSMEM);
    cudaFuncSetAttribute(hgemm_kernel<bf16>,  cudaFuncAttributeMaxDynamicSharedMemorySize, HSMEM);

    // pack + conversions
    pack_f_kernel<<<(DD*NN*RR + 255)/256, 256>>>(f_qk, Bqkv, RR, 2*NR, 0);
    pack_f_kernel<<<(DD*NN*RR + 255)/256, 256>>>(f_v,  Bqkv, RR, 2*NR, NR);
    pack_f_kernel<<<(DD*NN*RKK + 255)/256, 256>>>(f_know, Bkn, RKK, NRK, 0);
    transpose_kernel<<<dim3(32,32), dim3(32,8)>>>(W_O, WOT);
    cvt_bf16_kernel<<<(NR*DD + 255)/256, 256>>>(r_qk, rqk, NR*DD);
    cvt_bf16_kernel<<<(NR*DD + 255)/256, 256>>>(r_v,  rv,  NR*DD);
    cvt_bf16_kernel<<<(NRK*DD + 255)/256, 256>>>(r_know, rkn, NRK*DD);

    // --- attention circuit ---
    ln_kernel<<<BSZ, 256>>>(x, gamma1, beta1, nx);

    // fused feature GEMM: [4096 x 4096] = nx @ [Bqk|Bv]
    hgemm_kernel<float><<<dim3(2*NR/TN, BSZ/TM), 256, HSMEM>>>(nx, Bqkv, allh, nullptr, BSZ, 2*NR, DD);

    // fused combine+buildT
    combineT_kernel<<<BSZ, 256>>>(allh,      2*NR, w_fq, w_fk, w_rq, w_rk, Tqk, Tqk + (size_t)BSZ*NR, RR);
    combineT_kernel<<<BSZ, 256>>>(allh + NR, 2*NR, w_fv, nullptr, w_rv, nullptr, Tv, nullptr, RR);

    // fused Q+K restore (M=8192), V restore
    hgemm_kernel<bf16><<<dim3(DD/TN, 2*BSZ/TM), 256, HSMEM>>>(Tqk, rqk, QKb, nullptr, 2*BSZ, DD, NR);
    hgemm_kernel<bf16><<<dim3(DD/TN, BSZ/TM), 256, HSMEM>>>(Tv, rv, Vb, nullptr, BSZ, DD, NR);

    attn_mma_kernel<<<dim3(SS/64, HH, BB), 128>>>(QKb, QKb + (size_t)BSZ*DD, Vb, attn);

    // x1 = x + attn @ W_O^T
    hgemm_kernel<float><<<dim3(DD/TN, BSZ/TM), 256, HSMEM>>>(attn, WOT, x1, x, BSZ, DD, DD);

    // --- knowledge circuit ---
    ln_kernel<<<BSZ, 256>>>(x1, gamma2, beta2, nx);
    hgemm_kernel<float><<<dim3(NRK/TN, BSZ/TM), 256, HSMEM>>>(nx, Bkn, allh, nullptr, BSZ, NRK, DD);
    combineT_kernel<<<BSZ, 256>>>(allh, NRK, w_know_f, nullptr, w_know_r, nullptr, Tkn, nullptr, RKK);
    // out = x1 + Tkn @ r_know
    hgemm_kernel<float><<<dim3(DD/TN, BSZ/TM), 256, HSMEM>>>(Tkn, rkn, out, x1, BSZ, DD, NRK);
}

// round 9
// speedup vs baseline: 7.2816x; 1.1600x over previous
#include <cuda_runtime.h>
#include <cuda_bf16.h>
#include <math.h>
#include <stdint.h>

// Problem constants
#define BB 2
#define SS 2048
#define DD 1024
#define HH 16
#define RR 64
#define NN 32
#define RKK 128
#define DHH 64
#define BSZ (BB*SS)          // 4096 tokens
#define NR (NN*RR)           // 2048
#define NRK (NN*RKK)         // 4096
#define LN_EPS 1e-5f

typedef __nv_bfloat16 bf16;
typedef uint8_t fp8;

// quantization scales (powers of 2)
#define SQ_ACT  16.0f     // nx
#define SQ_W    512.0f    // f packs, r transposes, W_O
#define SQ_T    32.0f     // T outer products
#define SQ_ATTN 64.0f     // attention output
#define INV_FEAT (1.0f/(SQ_ACT*SQ_W))
#define INV_REST (1.0f/(SQ_T*SQ_W))
#define INV_WO   (1.0f/(SQ_ATTN*SQ_W))

// ---------------- scratch ----------------------------------------------------
__device__ fp8   g_BqkvT[(size_t)2*NR*DD];    // [2NR, D]  B^T feature (fp8)
__device__ fp8   g_BknT[(size_t)NRK*DD];      // [NRK, D]
__device__ fp8   g_WOb[(size_t)DD*DD];        // W_O (B^T of W_O^T)
__device__ fp8   g_rqkT[(size_t)DD*NR];       // r_qk^T [D, NR]
__device__ fp8   g_rvT [(size_t)DD*NR];
__device__ fp8   g_rknT[(size_t)DD*NRK];
__device__ fp8   g_nx [BSZ*DD];
__device__ float g_allh[(size_t)BSZ*4096];
__device__ fp8   g_Tqk[(size_t)2*BSZ*NR];     // [Tq ; Tk]
__device__ fp8   g_Tv [(size_t)BSZ*NR];
__device__ fp8   g_Tkn[(size_t)BSZ*NRK];
__device__ bf16  g_QKb[(size_t)2*BSZ*DD];     // [Q ; K] bf16 (attention input)
__device__ bf16  g_Vb[BSZ*DD];
__device__ fp8   g_attn[BSZ*DD];
__device__ float g_x1[BSZ*DD];

// ---------------- helpers ----------------------------------------------------
__device__ __forceinline__ uint32_t smem_u32(const void* p) {
    return (uint32_t)__cvta_generic_to_shared(p);
}
__device__ __forceinline__ void cp16(uint32_t saddr, const void* gaddr) {
    asm volatile("cp.async.cg.shared.global [%0], [%1], 16;\n" :: "r"(saddr), "l"(gaddr));
}
__device__ __forceinline__ void cp_commit() { asm volatile("cp.async.commit_group;\n"); }
template<int N> __device__ __forceinline__ void cp_wait() {
    asm volatile("cp.async.wait_group %0;\n" :: "n"(N));
}
__device__ __forceinline__ void ldsm_x4(uint32_t& r0, uint32_t& r1, uint32_t& r2, uint32_t& r3, uint32_t addr) {
    asm volatile("ldmatrix.sync.aligned.m8n8.x4.shared.b16 {%0,%1,%2,%3}, [%4];\n"
                 : "=r"(r0), "=r"(r1), "=r"(r2), "=r"(r3) : "r"(addr));
}
__device__ __forceinline__ void ldsm_x4_t(uint32_t& r0, uint32_t& r1, uint32_t& r2, uint32_t& r3, uint32_t addr) {
    asm volatile("ldmatrix.sync.aligned.m8n8.x4.trans.shared.b16 {%0,%1,%2,%3}, [%4];\n"
                 : "=r"(r0), "=r"(r1), "=r"(r2), "=r"(r3) : "r"(addr));
}
__device__ __forceinline__ void mma16816(float* d, const uint32_t* a, const uint32_t* b) {
    asm volatile("mma.sync.aligned.m16n8k16.row.col.f32.bf16.bf16.f32 "
                 "{%0,%1,%2,%3}, {%4,%5,%6,%7}, {%8,%9}, {%0,%1,%2,%3};\n"
                 : "+f"(d[0]), "+f"(d[1]), "+f"(d[2]), "+f"(d[3])
                 : "r"(a[0]), "r"(a[1]), "r"(a[2]), "r"(a[3]), "r"(b[0]), "r"(b[1]));
}
__device__ __forceinline__ void mma16832fp8(float* d, const uint32_t* a, const uint32_t* b) {
    asm volatile("mma.sync.aligned.m16n8k32.row.col.f32.e4m3.e4m3.f32 "
                 "{%0,%1,%2,%3}, {%4,%5,%6,%7}, {%8,%9}, {%0,%1,%2,%3};\n"
                 : "+f"(d[0]), "+f"(d[1]), "+f"(d[2]), "+f"(d[3])
                 : "r"(a[0]), "r"(a[1]), "r"(a[2]), "r"(a[3]), "r"(b[0]), "r"(b[1]));
}
__device__ __forceinline__ uint32_t pack_bf16(float x, float y) {
    __nv_bfloat162 t = __floats2bfloat162_rn(x, y);
    return *(uint32_t*)&t;
}
// packs lo -> low byte, hi -> high byte
__device__ __forceinline__ uint16_t pack_fp8x2(float lo, float hi) {
    uint16_t v;
    asm("cvt.rn.satfinite.e4m3x2.f32 %0, %1, %2;" : "=h"(v) : "f"(hi), "f"(lo));
    return v;
}
__device__ __forceinline__ fp8 cvt_fp8(float x) {
    uint16_t v;
    asm("cvt.rn.satfinite.e4m3x2.f32 %0, %1, %2;" : "=h"(v) : "f"(0.f), "f"(x));
    return (fp8)(v & 0xFF);
}

// ================== FP8 tensor-core GEMM =====================================
// C[M,Nc] = invs * (Aq[M,K] @ Btq[Nc,K]^T) (+Res); A,Bt e4m3 K-major.
// CTA 128x128, TK=64 bytes, 256 thr, 8 warps (2M x 4N), 2-stage cp.async.
#define QSTR 80

template<typename OutT>
__global__ __launch_bounds__(256, 2)
void qgemm_kernel(const fp8* __restrict__ A, const fp8* __restrict__ Bt,
                  OutT* __restrict__ C, const float* __restrict__ Res,
                  float invs, int M, int Nc, int K) {
    __shared__ fp8 As[2][128][QSTR];
    __shared__ fp8 Bs[2][128][QSTR];
    int tid = threadIdx.x;
    int lane = tid & 31;
    int warp = tid >> 5;
    int warp_m = warp & 1;      // 2 x 64 rows
    int warp_n = warp >> 1;     // 4 x 32 cols

    const fp8* Ab = A + (size_t)blockIdx.y * 128 * K;
    const fp8* Bb = Bt + (size_t)blockIdx.x * 128 * K;

    float acc[4][4][4];
    #pragma unroll
    for (int i = 0; i < 4; i++)
        #pragma unroll
        for (int j = 0; j < 4; j++)
            #pragma unroll
            for (int v = 0; v < 4; v++) acc[i][j][v] = 0.f;

    int ldrow = tid >> 1;             // 0..127
    int ldc   = (tid & 1) * 32;       // 0 or 32

    // prologue: stage 0
    {
        uint32_t sa = smem_u32(&As[0][ldrow][ldc]);
        uint32_t sb = smem_u32(&Bs[0][ldrow][ldc]);
        cp16(sa,      Ab + (size_t)ldrow * K + ldc);
        cp16(sa + 16, Ab + (size_t)ldrow * K + ldc + 16);
        cp16(sb,      Bb + (size_t)ldrow * K + ldc);
        cp16(sb + 16, Bb + (size_t)ldrow * K + ldc + 16);
    }
    cp_commit();

    int KT = K >> 6;
    for (int kt = 0; kt < KT; kt++) {
        if (kt + 1 < KT) {
            int st = (kt + 1) & 1;
            int k0 = (kt + 1) * 64;
            uint32_t sa = smem_u32(&As[st][ldrow][ldc]);
            uint32_t sb = smem_u32(&Bs[st][ldrow][ldc]);
            cp16(sa,      Ab + (size_t)ldrow * K + k0 + ldc);
            cp16(sa + 16, Ab + (size_t)ldrow * K + k0 + ldc + 16);
            cp16(sb,      Bb + (size_t)ldrow * K + k0 + ldc);
            cp16(sb + 16, Bb + (size_t)ldrow * K + k0 + ldc + 16);
            cp_commit();
            cp_wait<1>();
        } else {
            cp_wait<0>();
        }
        __syncthreads();
        int st = kt & 1;
        #pragma unroll
        for (int kk = 0; kk < 64; kk += 32) {
            uint32_t af[4][4];
            #pragma unroll
            for (int i = 0; i < 4; i++) {
                int row = warp_m * 64 + i * 16 + (lane & 15);
                int col = kk + (lane >> 4) * 16;
                ldsm_x4(af[i][0], af[i][1], af[i][2], af[i][3], smem_u32(&As[st][row][col]));
            }
            uint32_t bfr[4][2];
            #pragma unroll
            for (int np = 0; np < 2; np++) {
                int row = warp_n * 32 + np * 16 + (lane & 7) + ((lane & 16) ? 8 : 0);
                int col = kk + ((lane & 8) ? 16 : 0);
                uint32_t r0, r1, r2, r3;
                ldsm_x4(r0, r1, r2, r3, smem_u32(&Bs[st][row][col]));
                bfr[np*2][0] = r0; bfr[np*2][1] = r1;
                bfr[np*2+1][0] = r2; bfr[np*2+1][1] = r3;
            }
            #pragma unroll
            for (int i = 0; i < 4; i++)
                #pragma unroll
                for (int j = 0; j < 4; j++)
                    mma16832fp8(acc[i][j], af[i], bfr[j]);
        }
        __syncthreads();
    }

    size_t blockRow = (size_t)blockIdx.y * 128;
    size_t blockCol = (size_t)blockIdx.x * 128;
    #pragma unroll
    for (int i = 0; i < 4; i++) {
        size_t r0 = blockRow + warp_m * 64 + i * 16 + (lane >> 2);
        #pragma unroll
        for (int j = 0; j < 4; j++) {
            size_t c0 = blockCol + warp_n * 32 + j * 8 + (lane & 3) * 2;
            float a0 = acc[i][j][0] * invs, a1 = acc[i][j][1] * invs;
            float a2 = acc[i][j][2] * invs, a3 = acc[i][j][3] * invs;
            if constexpr (sizeof(OutT) == 4) {
                float2 v0 = make_float2(a0, a1);
                float2 v1 = make_float2(a2, a3);
                if (Res) {
                    const float2 q0 = *(const float2*)(Res + r0 * Nc + c0);
                    const float2 q1 = *(const float2*)(Res + (r0 + 8) * Nc + c0);
                    v0.x += q0.x; v0.y += q0.y; v1.x += q1.x; v1.y += q1.y;
                }
                *(float2*)((float*)C + r0 * Nc + c0) = v0;
                *(float2*)((float*)C + (r0 + 8) * Nc + c0) = v1;
            } else {
                *(uint32_t*)((bf16*)C + r0 * Nc + c0)       = pack_bf16(a0, a1);
                *(uint32_t*)((bf16*)C + (r0 + 8) * Nc + c0) = pack_bf16(a2, a3);
            }
        }
    }
}

// ---------------- pack f[n,d,r] -> fp8 out[(colOff + n*Rr + r)*D + d] --------
__global__ void pack_fT_kernel(const float* __restrict__ in, fp8* __restrict__ out,
                               int Rr, int colOff) {
    int total = DD * NN * Rr;
    int idx = blockIdx.x * blockDim.x + threadIdx.x;
    if (idx >= total) return;
    int d = idx & (DD - 1);
    int col = idx >> 10;
    int n = col / Rr;
    int r = col - n * Rr;
    out[(size_t)(colOff + col) * DD + d] = cvt_fp8(in[((size_t)n * DD + d) * Rr + r] * SQ_W);
}

__global__ void cvt_fp8_kernel(const float* __restrict__ in, fp8* __restrict__ out, int n) {
    int i = blockIdx.x * blockDim.x + threadIdx.x;
    if (i < n) out[i] = cvt_fp8(in[i] * SQ_W);
}

// transpose + fp8: in [rows, cols] fp32 -> out [cols, rows] fp8 (x SQ_W)
__global__ void transpose_q_kernel(const float* __restrict__ in, fp8* __restrict__ out,
                                   int rows, int cols) {
    __shared__ float tile[32][33];
    int x = blockIdx.x * 32 + threadIdx.x;
    int y = blockIdx.y * 32 + threadIdx.y;
    #pragma unroll
    for (int i = 0; i < 32; i += 8)
        tile[threadIdx.y + i][threadIdx.x] = in[(size_t)(y + i) * cols + x];
    __syncthreads();
    x = blockIdx.y * 32 + threadIdx.x;
    y = blockIdx.x * 32 + threadIdx.y;
    #pragma unroll
    for (int i = 0; i < 32; i += 8)
        out[(size_t)(y + i) * rows + x] = cvt_fp8(tile[threadIdx.x][threadIdx.y + i] * SQ_W);
}

// ---------------- LayerNorm (fp8 out, x SQ_ACT) ------------------------------
__global__ void ln_kernel(const float* __restrict__ x, const float* __restrict__ g,
                          const float* __restrict__ b, fp8* __restrict__ out) {
    int row = blockIdx.x;
    const float* xr = x + (size_t)row * DD;
    int c = threadIdx.x * 4;
    float4 xv = *(const float4*)(xr + c);
    float s  = xv.x + xv.y + xv.z + xv.w;
    float sq = xv.x*xv.x + xv.y*xv.y + xv.z*xv.z + xv.w*xv.w;
    #pragma unroll
    for (int o = 16; o > 0; o >>= 1) {
        s  += __shfl_xor_sync(0xffffffffu, s,  o);
        sq += __shfl_xor_sync(0xffffffffu, sq, o);
    }
    __shared__ float ss[8], ssq[8];
    __shared__ float mean_s, rstd_s;
    int wid = threadIdx.x >> 5, lid = threadIdx.x & 31;
    if (lid == 0) { ss[wid] = s; ssq[wid] = sq; }
    __syncthreads();
    if (threadIdx.x == 0) {
        float S = 0.f, SQ = 0.f;
        #pragma unroll
        for (int i = 0; i < 8; i++) { S += ss[i]; SQ += ssq[i]; }
        float mu  = S * (1.f / DD);
        float var = SQ * (1.f / DD) - mu * mu;
        mean_s = mu;
        rstd_s = rsqrtf(var + LN_EPS);
    }
    __syncthreads();
    float mu = mean_s, rs = rstd_s;
    float4 gv = *(const float4*)(g + c);
    float4 bv = *(const float4*)(b + c);
    float o0 = (gv.x * (xv.x - mu) * rs + bv.x) * SQ_ACT;
    float o1 = (gv.y * (xv.y - mu) * rs + bv.y) * SQ_ACT;
    float o2 = (gv.z * (xv.z - mu) * rs + bv.z) * SQ_ACT;
    float o3 = (gv.w * (xv.w - mu) * rs + bv.w) * SQ_ACT;
    uint32_t pk = (uint32_t)pack_fp8x2(o0, o1) | ((uint32_t)pack_fp8x2(o2, o3) << 16);
    *(uint32_t*)(out + (size_t)row * DD + c) = pk;
}

// ---------------- fused combine + buildT (fp8 T out, x SQ_T) -----------------
__global__ void combineT_kernel(const float* __restrict__ allh, int stride,
                                const float* __restrict__ wf1, const float* __restrict__ wf2,
                                const float* __restrict__ wr1, const float* __restrict__ wr2,
                                fp8* __restrict__ T1, fp8* __restrict__ T2, int Rr) {
    int bs = blockIdx.x;
    int tid = threadIdx.x;
    __shared__ float h1s[RKK], h2s[RKK];
    __shared__ float wf1s[NN], wf2s[NN], wr1s[NN], wr2s[NN];
    if (tid < NN) {
        wf1s[tid] = wf1[(size_t)bs * NN + tid];
        wr1s[tid] = wr1[(size_t)bs * NN + tid] * SQ_T;
        if (wf2) { wf2s[tid] = wf2[(size_t)bs * NN + tid]; wr2s[tid] = wr2[(size_t)bs * NN + tid] * SQ_T; }
    }
    __syncthreads();
    if (tid < Rr) {
        const float* rowp = allh + (size_t)bs * stride;
        float a1 = 0.f, a2 = 0.f;
        #pragma unroll 8
        for (int n = 0; n < NN; n++) {
            float v = rowp[n * Rr + tid];
            a1 += wf1s[n] * v;
            if (wf2) a2 += wf2s[n] * v;
        }
        h1s[tid] = a1;
        if (wf2) h2s[tid] = a2;
    }
    __syncthreads();
    int total = NN * Rr;
    fp8* T1row = T1 + (size_t)bs * total;
    fp8* T2row = wf2 ? (T2 + (size_t)bs * total) : nullptr;
    for (int i = tid; i < total; i += 256) {
        int n = i / Rr;
        int r = i - n * Rr;
        T1row[i] = cvt_fp8(wr1s[n] * h1s[r]);
        if (wf2) T2row[i] = cvt_fp8(wr2s[n] * h2s[r]);
    }
}

// ================= bf16 mma.sync flash attention (fp8 output) ================
#define KSTR 72
#define SC2 (0.125f * 1.44269504f)

__global__ __launch_bounds__(128)
void attn_mma_kernel(const bf16* __restrict__ Q, const bf16* __restrict__ K,
                     const bf16* __restrict__ V, fp8* __restrict__ O) {
    __shared__ bf16 Qs[64][KSTR];
    __shared__ bf16 Ks[2][64][KSTR];
    __shared__ bf16 Vs[2][64][KSTR];

    int qt = gridDim.x - 1 - blockIdx.x;
    int h = blockIdx.y, b = blockIdx.z;
    int tid = threadIdx.x;
    int lane = tid & 31, w = tid >> 5;
    size_t headoff = (size_t)h * DHH;

    const bf16* Qbase = Q + ((size_t)(b * SS + qt * 64)) * DD + headoff;
    const bf16* Kbase = K + ((size_t)b * SS) * DD + headoff;
    const bf16* Vbase = V + ((size_t)b * SS) * DD + headoff;

    #pragma unroll
    for (int i = 0; i < 4; i++) {
        int c = tid + i * 128;
        int row = c >> 3, off = (c & 7) * 8;
        cp16(smem_u32(&Qs[row][off]), Qbase + (size_t)row * DD + off);
    }
    cp_commit();
    #pragma unroll
    for (int i = 0; i < 4; i++) {
        int c = tid + i * 128;
        int row = c >> 3, off = (c & 7) * 8;
        cp16(smem_u32(&Ks[0][row][off]), Kbase + (size_t)row * DD + off);
        cp16(smem_u32(&Vs[0][row][off]), Vbase + (size_t)row * DD + off);
    }
    cp_commit();

    cp_wait<1>();
    __syncthreads();
    uint32_t aq[4][4];
    #pragma unroll
    for (int kc = 0; kc < 4; kc++) {
        int row = w * 16 + (lane & 15);
        int col = kc * 16 + (lane >> 4) * 8;
        ldsm_x4(aq[kc][0], aq[kc][1], aq[kc][2], aq[kc][3], smem_u32(&Qs[row][col]));
    }

    float acc_o[8][4];
    #pragma unroll
    for (int nt = 0; nt < 8; nt++)
        #pragma unroll
        for (int v = 0; v < 4; v++) acc_o[nt][v] = 0.f;
    float m[2] = {-INFINITY, -INFINITY};
    float l[2] = {0.f, 0.f};

    int ntiles = qt + 1;
    for (int j = 0; j < ntiles; j++) {
        int st = j & 1;
        if (j + 1 < ntiles) {
            const bf16* kb = Kbase + (size_t)(j + 1) * 64 * DD;
            const bf16* vb = Vbase + (size_t)(j + 1) * 64 * DD;
            #pragma unroll
            for (int i = 0; i < 4; i++) {
                int c = tid + i * 128;
                int row = c >> 3, off = (c & 7) * 8;
                cp16(smem_u32(&Ks[st ^ 1][row][off]), kb + (size_t)row * DD + off);
                cp16(smem_u32(&Vs[st ^ 1][row][off]), vb + (size_t)row * DD + off);
            }
            cp_commit();
            cp_wait<1>();
        } else {
            cp_wait<0>();
        }
        __syncthreads();

        float s[8][4];
        #pragma unroll
        for (int nt = 0; nt < 8; nt++)
            #pragma unroll
            for (int v = 0; v < 4; v++) s[nt][v] = 0.f;
        #pragma unroll
        for (int kc = 0; kc < 4; kc++) {
            uint32_t bk[8][2];
            #pragma unroll
            for (int np = 0; np < 4; np++) {
                int row = np * 16 + (lane & 7) + ((lane & 16) ? 8 : 0);
                int colk = kc * 16 + ((lane & 8) ? 8 : 0);
                uint32_t r0, r1, r2, r3;
                ldsm_x4(r0, r1, r2, r3, smem_u32(&Ks[st][row][colk]));
                bk[np*2][0] = r0; bk[np*2][1] = r1;
                bk[np*2+1][0] = r2; bk[np*2+1][1] = r3;
            }
            #pragma unroll
            for (int nt = 0; nt < 8; nt++)
                mma16816(s[nt], aq[kc], bk[nt]);
        }

        if (j == qt) {
            int r0 = w * 16 + (lane >> 2);
            int cb = (lane & 3) * 2;
            #pragma unroll
            for (int nt = 0; nt < 8; nt++) {
                #pragma unroll
                for (int v = 0; v < 4; v++) {
                    int col = nt * 8 + cb + (v & 1);
                    int row = r0 + ((v & 2) ? 8 : 0);
                    if (col > row) s[nt][v] = -INFINITY;
                }
            }
        }

        #pragma unroll
        for (int rh = 0; rh < 2; rh++) {
            float mt = -INFINITY;
            #pragma unroll
            for (int nt = 0; nt < 8; nt++)
                mt = fmaxf(mt, fmaxf(s[nt][rh*2], s[nt][rh*2+1]));
            mt = fmaxf(mt, __shfl_xor_sync(0xffffffffu, mt, 1));
            mt = fmaxf(mt, __shfl_xor_sync(0xffffffffu, mt, 2));
            float mn = fmaxf(m[rh], mt);
            float corr = exp2f((m[rh] - mn) * SC2);
            m[rh] = mn;
            float ls = 0.f;
            #pragma unroll
            for (int nt = 0; nt < 8; nt++) {
                float p0 = exp2f((s[nt][rh*2]   - mn) * SC2);
                float p1 = exp2f((s[nt][rh*2+1] - mn) * SC2);
                s[nt][rh*2] = p0; s[nt][rh*2+1] = p1;
                ls += p0 + p1;
            }
            ls += __shfl_xor_sync(0xffffffffu, ls, 1);
            ls += __shfl_xor_sync(0xffffffffu, ls, 2);
            l[rh] = l[rh] * corr + ls;
            #pragma unroll
            for (int nt = 0; nt < 8; nt++) {
                acc_o[nt][rh*2]   *= corr;
                acc_o[nt][rh*2+1] *= corr;
            }
        }

        #pragma unroll
        for (int kc = 0; kc < 4; kc++) {
            uint32_t pa[4];
            pa[0] = pack_bf16(s[2*kc][0],   s[2*kc][1]);
            pa[1] = pack_bf16(s[2*kc][2],   s[2*kc][3]);
            pa[2] = pack_bf16(s[2*kc+1][0], s[2*kc+1][1]);
            pa[3] = pack_bf16(s[2*kc+1][2], s[2*kc+1][3]);
            uint32_t bv[8][2];
            #pragma unroll
            for (int np = 0; np < 4; np++) {
                int kr = kc * 16 + (lane & 7) + ((lane & 16) ? 8 : 0);
                int col = np * 16 + ((lane & 8) ? 8 : 0);
                uint32_t r0, r1, r2, r3;
                ldsm_x4_t(r0, r1, r2, r3, smem_u32(&Vs[st][kr][col]));
                bv[np*2][0] = r0; bv[np*2+1][0] = r1;
                bv[np*2][1] = r2; bv[np*2+1][1] = r3;
            }
            #pragma unroll
            for (int nt = 0; nt < 8; nt++)
                mma16816(acc_o[nt], pa, bv[nt]);
        }
        __syncthreads();
    }

    float inv0 = SQ_ATTN / l[0];
    float inv1 = SQ_ATTN / l[1];
    int row0 = qt * 64 + w * 16 + (lane >> 2);
    fp8* Ob = O + ((size_t)b * SS) * DD + headoff;
    #pragma unroll
    for (int nt = 0; nt < 8; nt++) {
        int col = nt * 8 + (lane & 3) * 2;
        *(uint16_t*)(Ob + (size_t)row0 * DD + col)       = pack_fp8x2(acc_o[nt][0] * inv0, acc_o[nt][1] * inv0);
        *(uint16_t*)(Ob + (size_t)(row0 + 8) * DD + col) = pack_fp8x2(acc_o[nt][2] * inv1, acc_o[nt][3] * inv1);
    }
}

// ---------------- launch -----------------------------------------------------
extern "C" void kernel_launch(void* const* d_in, const int* in_sizes, int n_in,
                              void* d_out, int out_size) {
    const float* x       = (const float*)d_in[0];
    const float* f_qk    = (const float*)d_in[1];
    const float* f_v     = (const float*)d_in[2];
    const float* r_qk    = (const float*)d_in[3];
    const float* r_v     = (const float*)d_in[4];
    const float* f_know  = (const float*)d_in[5];
    const float* r_know  = (const float*)d_in[6];
    const float* W_O     = (const float*)d_in[7];
    const float* gamma1  = (const float*)d_in[8];
    const float* beta1   = (const float*)d_in[9];
    const float* gamma2  = (const float*)d_in[10];
    const float* beta2   = (const float*)d_in[11];
    const float* w_fq    = (const float*)d_in[12];
    const float* w_fk    = (const float*)d_in[13];
    const float* w_fv    = (const float*)d_in[14];
    const float* w_rq    = (const float*)d_in[15];
    const float* w_rk    = (const float*)d_in[16];
    const float* w_rv    = (const float*)d_in[17];
    const float* w_know_f= (const float*)d_in[18];
    const float* w_know_r= (const float*)d_in[19];
    float* out = (float*)d_out;

    fp8 *BqkvT, *BknT, *WOb, *rqkT, *rvT, *rknT, *nx, *Tqk, *Tv, *Tkn, *attn;
    bf16 *QKb, *Vb;
    float *allh, *x1;
    cudaGetSymbolAddress((void**)&BqkvT, g_BqkvT);
    cudaGetSymbolAddress((void**)&BknT, g_BknT);
    cudaGetSymbolAddress((void**)&WOb, g_WOb);
    cudaGetSymbolAddress((void**)&rqkT, g_rqkT);
    cudaGetSymbolAddress((void**)&rvT,  g_rvT);
    cudaGetSymbolAddress((void**)&rknT, g_rknT);
    cudaGetSymbolAddress((void**)&nx,  g_nx);
    cudaGetSymbolAddress((void**)&allh, g_allh);
    cudaGetSymbolAddress((void**)&Tqk, g_Tqk);
    cudaGetSymbolAddress((void**)&Tv,  g_Tv);
    cudaGetSymbolAddress((void**)&Tkn, g_Tkn);
    cudaGetSymbolAddress((void**)&QKb, g_QKb);
    cudaGetSymbolAddress((void**)&Vb,  g_Vb);
    cudaGetSymbolAddress((void**)&attn, g_attn);
    cudaGetSymbolAddress((void**)&x1, g_x1);

    // operand prep (B^T layouts, K-major, fp8)
    pack_fT_kernel<<<(DD*NN*RR + 255)/256, 256>>>(f_qk, BqkvT, RR, 0);
    pack_fT_kernel<<<(DD*NN*RR + 255)/256, 256>>>(f_v,  BqkvT, RR, NR);
    pack_fT_kernel<<<(DD*NN*RKK + 255)/256, 256>>>(f_know, BknT, RKK, 0);
    cvt_fp8_kernel<<<(DD*DD + 255)/256, 256>>>(W_O, WOb, DD*DD);
    transpose_q_kernel<<<dim3(DD/32, NR/32),  dim3(32,8)>>>(r_qk,   rqkT, NR,  DD);
    transpose_q_kernel<<<dim3(DD/32, NR/32),  dim3(32,8)>>>(r_v,    rvT,  NR,  DD);
    transpose_q_kernel<<<dim3(DD/32, NRK/32), dim3(32,8)>>>(r_know, rknT, NRK, DD);

    // --- attention circuit ---
    ln_kernel<<<BSZ, 256>>>(x, gamma1, beta1, nx);

    // feature GEMM: allh[4096,4096] = nx @ [f_qk|f_v]
    qgemm_kernel<float><<<dim3(2*NR/128, BSZ/128), 256>>>(nx, BqkvT, allh, nullptr, INV_FEAT, BSZ, 2*NR, DD);

    combineT_kernel<<<BSZ, 256>>>(allh,      2*NR, w_fq, w_fk, w_rq, w_rk, Tqk, Tqk + (size_t)BSZ*NR, RR);
    combineT_kernel<<<BSZ, 256>>>(allh + NR, 2*NR, w_fv, nullptr, w_rv, nullptr, Tv, nullptr, RR);

    // restore GEMMs (QK fused M=8192; V) -> bf16
    qgemm_kernel<bf16><<<dim3(DD/128, 2*BSZ/128), 256>>>(Tqk, rqkT, QKb, nullptr, INV_REST, 2*BSZ, DD, NR);
    qgemm_kernel<bf16><<<dim3(DD/128, BSZ/128), 256>>>(Tv, rvT, Vb, nullptr, INV_REST, BSZ, DD, NR);

    attn_mma_kernel<<<dim3(SS/64, HH, BB), 128>>>(QKb, QKb + (size_t)BSZ*DD, Vb, attn);

    // x1 = x + attn @ W_O^T  (B^T = W_O)
    qgemm_kernel<float><<<dim3(DD/128, BSZ/128), 256>>>(attn, WOb, x1, x, INV_WO, BSZ, DD, DD);

    // --- knowledge circuit ---
    ln_kernel<<<BSZ, 256>>>(x1, gamma2, beta2, nx);
    qgemm_kernel<float><<<dim3(NRK/128, BSZ/128), 256>>>(nx, BknT, allh, nullptr, INV_FEAT, BSZ, NRK, DD);
    combineT_kernel<<<BSZ, 256>>>(allh, NRK, w_know_f, nullptr, w_know_r, nullptr, Tkn, nullptr, RKK);
    qgemm_kernel<float><<<dim3(DD/128, BSZ/128), 256>>>(Tkn, rknT, out, x1, INV_REST, BSZ, DD, NRK);
}